// round 2
// baseline (speedup 1.0000x reference)
#include <cuda_runtime.h>
#include <math.h>

#define SEQ   4096
#define BATCH 4
#define DIMN  1024
#define NH    16
#define DHD   64
#define LLC   32
#define WWIN  8
#define EEXT  4
#define BAND  16
#define NGRP  512
#define MROWS (SEQ*BATCH)   // 16384
#define HL    512           // H*L

// ---------------- scratch (device globals: allocation-free) ----------------
__device__ float g_Q[(size_t)MROWS*DIMN];
__device__ float g_K[(size_t)MROWS*DIMN];
__device__ float g_V[(size_t)MROWS*DIMN];
__device__ float g_D[(size_t)MROWS*HL];
__device__ float g_cmax[BATCH*HL];
__device__ float g_cinv[BATCH*HL];
__device__ float g_Kc[BATCH*NH*LLC*DHD];
__device__ float g_Vc[BATCH*NH*LLC*DHD];
__device__ float g_C[(size_t)MROWS*DIMN];

// ---------------- generic fp32 GEMM: C = alpha*(A@B + bias) ----------------
// M=16384, K=1024 fixed. MODE 0: A rows come from query layout (S,B,DIM),
// C written plain (r*N). MODE 1: A plain, C scattered to (s*B+b)*DIMN.
template<int MODE>
__global__ __launch_bounds__(256) void sgemm(
    const float* __restrict__ A, const float* __restrict__ Bw,
    const float* __restrict__ bias, float* __restrict__ Cout,
    int N, float alpha)
{
    __shared__ float As[8][128];
    __shared__ float Bs[8][128];

    const int tid = threadIdx.x;
    const int bx = blockIdx.x, by = blockIdx.y;

    const int arow = tid >> 1;
    const int acol = (tid & 1) << 2;
    const int gr = by*128 + arow;
    const float* Aptr;
    if (MODE == 0) {
        int bb = gr >> 12, ss = gr & 4095;
        Aptr = A + ((size_t)(ss*BATCH + bb))*DIMN + acol;
    } else {
        Aptr = A + (size_t)gr*DIMN + acol;
    }
    const int brow = tid >> 5;
    const int bcol = (tid & 31) << 2;
    const float* Bptr = Bw + (size_t)brow*N + bx*128 + bcol;

    float acc[8][8];
    #pragma unroll
    for (int i=0;i<8;i++)
        #pragma unroll
        for (int j=0;j<8;j++) acc[i][j]=0.f;

    const int tx = tid & 15, ty = tid >> 4;

    for (int k0 = 0; k0 < DIMN; k0 += 8) {
        float4 av = *(const float4*)(Aptr + k0);
        As[acol+0][arow]=av.x; As[acol+1][arow]=av.y;
        As[acol+2][arow]=av.z; As[acol+3][arow]=av.w;
        *(float4*)&Bs[brow][bcol] = *(const float4*)(Bptr + (size_t)k0*N);
        __syncthreads();
        #pragma unroll
        for (int kk=0;kk<8;kk++){
            float ar[8], br[8];
            *(float4*)&ar[0] = *(const float4*)&As[kk][ty*8];
            *(float4*)&ar[4] = *(const float4*)&As[kk][ty*8+4];
            *(float4*)&br[0] = *(const float4*)&Bs[kk][tx*8];
            *(float4*)&br[4] = *(const float4*)&Bs[kk][tx*8+4];
            #pragma unroll
            for (int i=0;i<8;i++)
                #pragma unroll
                for (int j=0;j<8;j++)
                    acc[i][j] += ar[i]*br[j];
        }
        __syncthreads();
    }

    #pragma unroll
    for (int i=0;i<8;i++){
        int rr = by*128 + ty*8 + i;
        size_t outbase;
        if (MODE == 0) outbase = (size_t)rr*N;
        else { int bb = rr>>12, ss = rr&4095; outbase = ((size_t)(ss*BATCH+bb))*DIMN; }
        #pragma unroll
        for (int j=0;j<8;j++){
            int n = bx*128 + tx*8 + j;
            Cout[outbase + n] = alpha*(acc[i][j] + bias[n]);
        }
    }
}

// ---------------- row layernorm over DIM=1024 (in-place) ----------------
__global__ __launch_bounds__(256) void ln_rows(
    float* __restrict__ X, const float* __restrict__ gamma,
    const float* __restrict__ beta)
{
    int row = blockIdx.x;
    float* p = X + (size_t)row*DIMN;
    int tid = threadIdx.x;
    float4 v = *(float4*)(p + tid*4);
    float s  = v.x+v.y+v.z+v.w;
    float s2 = v.x*v.x+v.y*v.y+v.z*v.z+v.w*v.w;
    #pragma unroll
    for (int o=16;o>0;o>>=1){
        s  += __shfl_down_sync(0xffffffffu, s,  o);
        s2 += __shfl_down_sync(0xffffffffu, s2, o);
    }
    __shared__ float rs[8], rs2[8];
    int warp = tid>>5, lane = tid&31;
    if (lane==0){ rs[warp]=s; rs2[warp]=s2; }
    __syncthreads();
    if (tid==0){
        float S=0.f,S2=0.f;
        for(int i=0;i<8;i++){S+=rs[i];S2+=rs2[i];}
        float mean = S*(1.f/DIMN);
        float var  = S2*(1.f/DIMN) - mean*mean;
        rs[0]=mean; rs2[0]=rsqrtf(var + 1e-5f);
    }
    __syncthreads();
    float mean = rs[0], rstd = rs2[0];
    float4 g4 = *(const float4*)(gamma + tid*4);
    float4 b4 = *(const float4*)(beta  + tid*4);
    v.x = (v.x-mean)*rstd*g4.x + b4.x;
    v.y = (v.y-mean)*rstd*g4.y + b4.y;
    v.z = (v.z-mean)*rstd*g4.z + b4.z;
    v.w = (v.w-mean)*rstd*g4.w + b4.w;
    *(float4*)(p + tid*4) = v;
}

// ------- column softmax stats over sequence axis of D (B,S,512) -------
__global__ __launch_bounds__(256) void colstats()
{
    int b  = blockIdx.x >> 4;
    int c0 = (blockIdx.x & 15) << 5;
    int cl = threadIdx.x & 31;
    int si = threadIdx.x >> 5;    // 0..7
    int c = c0 + cl;
    float m = -1e30f, sum = 0.f;
    for (int s = si; s < SEQ; s += 8){
        float v = g_D[((size_t)(b*SEQ + s))*HL + c];
        if (v > m){ sum *= __expf(m - v); m = v; }
        sum += __expf(v - m);
    }
    __shared__ float sm[8][32], ss[8][32];
    sm[si][cl]=m; ss[si][cl]=sum;
    __syncthreads();
    if (si == 0){
        float M = sm[0][cl];
        #pragma unroll
        for (int k=1;k<8;k++) M = fmaxf(M, sm[k][cl]);
        float S = 0.f;
        #pragma unroll
        for (int k=0;k<8;k++) S += ss[k][cl]*__expf(sm[k][cl]-M);
        g_cmax[b*HL + c] = M;
        g_cinv[b*HL + c] = 1.f/S;
    }
}

// ----- compressed landmarks: Kc/Vc[b,h,l,d] = sum_s softmax_w * K/V -----
__global__ __launch_bounds__(256) void compress()
{
    int b = blockIdx.x >> 4;
    int h = blockIdx.x & 15;
    int tid = threadIdx.x;
    int d  = tid & 63;
    int lg = tid >> 6;      // 0..3 -> l = lg*8 + i
    __shared__ float wsh[8][32];
    __shared__ float ksh[8][64];
    __shared__ float vsh[8][64];
    __shared__ float msh[32], ish[32];
    if (tid < 32){
        msh[tid] = g_cmax[b*HL + h*32 + tid];
        ish[tid] = g_cinv[b*HL + h*32 + tid];
    }
    __syncthreads();
    float kacc[8], vacc[8];
    #pragma unroll
    for (int i=0;i<8;i++){ kacc[i]=0.f; vacc[i]=0.f; }

    for (int s0=0; s0<SEQ; s0+=8){
        {
            int si = tid >> 5, l = tid & 31;
            float dv = g_D[((size_t)(b*SEQ + s0 + si))*HL + h*32 + l];
            wsh[si][l] = __expf(dv - msh[l]) * ish[l];
        }
        #pragma unroll
        for (int r=0;r<2;r++){
            int e = tid + r*256;
            int si = e >> 6, dd = e & 63;
            size_t off = ((size_t)(b*SEQ + s0 + si))*DIMN + h*64 + dd;
            ksh[si][dd] = g_K[off];
            vsh[si][dd] = g_V[off];
        }
        __syncthreads();
        #pragma unroll
        for (int si=0; si<8; si++){
            float kv = ksh[si][d], vv = vsh[si][d];
            #pragma unroll
            for (int i=0;i<8;i++){
                float w = wsh[si][lg*8+i];
                kacc[i] += w*kv; vacc[i] += w*vv;
            }
        }
        __syncthreads();
    }
    #pragma unroll
    for (int i=0;i<8;i++){
        int l = lg*8+i;
        size_t off = (((size_t)(b*NH+h))*LLC + l)*DHD + d;
        g_Kc[off] = kacc[i];
        g_Vc[off] = vacc[i];
    }
}

// ---- layernorm of Kc/Vc over (h,d) for each (b,l), gamma/beta g_s,b_s ----
__global__ __launch_bounds__(256) void ln_small(
    float* __restrict__ X, const float* __restrict__ gamma,
    const float* __restrict__ beta)
{
    int b = blockIdx.x >> 5;
    int l = blockIdx.x & 31;
    int tid = threadIdx.x;
    float vals[4];
    float s=0.f, s2=0.f;
    #pragma unroll
    for (int k=0;k<4;k++){
        int e = tid + k*256;
        int h = e >> 6, dd = e & 63;
        float v = X[(((size_t)(b*NH+h))*LLC + l)*DHD + dd];
        vals[k]=v; s+=v; s2+=v*v;
    }
    #pragma unroll
    for (int o=16;o>0;o>>=1){
        s  += __shfl_down_sync(0xffffffffu, s,  o);
        s2 += __shfl_down_sync(0xffffffffu, s2, o);
    }
    __shared__ float rs[8], rs2[8];
    int warp = tid>>5, lane = tid&31;
    if (lane==0){ rs[warp]=s; rs2[warp]=s2; }
    __syncthreads();
    if (tid==0){
        float S=0.f,S2=0.f;
        for(int i=0;i<8;i++){S+=rs[i];S2+=rs2[i];}
        float mean = S*(1.f/DIMN);
        float var  = S2*(1.f/DIMN) - mean*mean;
        rs[0]=mean; rs2[0]=rsqrtf(var + 1e-5f);
    }
    __syncthreads();
    float mean = rs[0], rstd = rs2[0];
    #pragma unroll
    for (int k=0;k<4;k++){
        int e = tid + k*256;
        int h = e >> 6, dd = e & 63;
        X[(((size_t)(b*NH+h))*LLC + l)*DHD + dd] =
            (vals[k]-mean)*rstd*gamma[e] + beta[e];
    }
}

// ---------------- fused attention: 32 compressed + 16 window keys ----------------
#define PADW 68
__global__ __launch_bounds__(128) void attn()
{
    int g = blockIdx.x, h = blockIdx.y, b = blockIdx.z;
    __shared__ float qsh[8][PADW];
    __shared__ float kc[32][PADW];
    __shared__ float vc[32][PADW];
    __shared__ float kt[16][PADW];
    __shared__ float vt[16][PADW];
    __shared__ float logit[8][48];
    __shared__ float prob[8][48];
    int tid = threadIdx.x;

    {   // Q tile: 8 x 64
        int w = tid>>4, c=(tid&15)<<2;
        *(float4*)&qsh[w][c] =
            *(const float4*)&g_Q[((size_t)(b*SEQ + g*8 + w))*DIMN + h*64 + c];
    }
    #pragma unroll
    for (int r=0;r<4;r++){   // Kc/Vc: 32 x 64 each
        int e = tid + r*128;
        int l = e>>4, c=(e&15)<<2;
        size_t off = (((size_t)(b*NH+h))*LLC + l)*DHD + c;
        *(float4*)&kc[l][c] = *(const float4*)&g_Kc[off];
        *(float4*)&vc[l][c] = *(const float4*)&g_Vc[off];
    }
    #pragma unroll
    for (int r=0;r<2;r++){   // window tiles: 16 x 64
        int e = tid + r*128;
        int j = e>>4, c=(e&15)<<2;
        int pos = g*WWIN - EEXT + j;
        float4 kz = make_float4(0,0,0,0), vz = make_float4(0,0,0,0);
        if (pos >= 0 && pos < SEQ){
            size_t off = ((size_t)(b*SEQ+pos))*DIMN + h*64 + c;
            kz = *(const float4*)&g_K[off];
            vz = *(const float4*)&g_V[off];
        }
        *(float4*)&kt[j][c] = kz;
        *(float4*)&vt[j][c] = vz;
    }
    __syncthreads();

    #pragma unroll
    for (int r=0;r<3;r++){   // 384 dots of length 64
        int t = tid + r*128;
        int w = t/48, j = t%48;
        float acc = 0.f;
        const float* kp = (j<32) ? &kc[j][0] : &kt[j-32][0];
        #pragma unroll
        for (int c=0;c<64;c++) acc += qsh[w][c]*kp[c];
        if (j>=32){
            int pos = g*WWIN - EEXT + (j-32);
            if (pos < 0 || pos >= SEQ) acc = -1e30f;
        }
        logit[w][j] = acc;
    }
    __syncthreads();

    if (tid < 8){
        int w = tid;
        float m = -1e30f;
        for (int j=0;j<48;j++) m = fmaxf(m, logit[w][j]);
        float ssum = 0.f;
        for (int j=0;j<48;j++){ float p = __expf(logit[w][j]-m); prob[w][j]=p; ssum+=p; }
        float inv = 1.f/ssum;
        for (int j=0;j<48;j++) prob[w][j] *= inv;
    }
    __syncthreads();

    #pragma unroll
    for (int r=0;r<4;r++){   // 8 x 64 outputs
        int t = tid + r*128;
        int w = t>>6, dd = t&63;
        float acc = 0.f;
        #pragma unroll
        for (int j=0;j<32;j++) acc += prob[w][j]*vc[j][dd];
        #pragma unroll
        for (int j=0;j<16;j++) acc += prob[w][32+j]*vt[j][dd];
        g_C[((size_t)(b*SEQ + g*8 + w))*DIMN + h*64 + dd] = acc;
    }
}

// ---------------- launch ----------------
extern "C" void kernel_launch(void* const* d_in, const int* in_sizes, int n_in,
                              void* d_out, int out_size)
{
    const float* query = (const float*)d_in[0];
    const float* Wq = (const float*)d_in[1];
    const float* bq = (const float*)d_in[2];
    const float* Wk = (const float*)d_in[3];
    const float* bk = (const float*)d_in[4];
    const float* Wv = (const float*)d_in[5];
    const float* bv = (const float*)d_in[6];
    const float* Wo = (const float*)d_in[7];
    const float* bo = (const float*)d_in[8];
    const float* gl = (const float*)d_in[9];
    const float* bl = (const float*)d_in[10];
    const float* gs = (const float*)d_in[11];
    const float* bs = (const float*)d_in[12];
    const float* Wd = (const float*)d_in[13];
    const float* bd = (const float*)d_in[14];
    float* out = (float*)d_out;

    float *Qp, *Kp, *Vp, *Dp, *Cp, *Kcp, *Vcp;
    cudaGetSymbolAddress((void**)&Qp,  g_Q);
    cudaGetSymbolAddress((void**)&Kp,  g_K);
    cudaGetSymbolAddress((void**)&Vp,  g_V);
    cudaGetSymbolAddress((void**)&Dp,  g_D);
    cudaGetSymbolAddress((void**)&Cp,  g_C);
    cudaGetSymbolAddress((void**)&Kcp, g_Kc);
    cudaGetSymbolAddress((void**)&Vcp, g_Vc);

    // projections
    sgemm<0><<<dim3(8,128), 256>>>(query, Wq, bq, Qp, DIMN, 0.125f);
    sgemm<0><<<dim3(8,128), 256>>>(query, Wk, bk, Kp, DIMN, 1.f);
    sgemm<0><<<dim3(8,128), 256>>>(query, Wv, bv, Vp, DIMN, 1.f);
    sgemm<0><<<dim3(4,128), 256>>>(query, Wd, bd, Dp, HL,   1.f);

    // K/V layernorm (g_l, b_l)
    ln_rows<<<MROWS, 256>>>(Kp, gl, bl);
    ln_rows<<<MROWS, 256>>>(Vp, gl, bl);

    // head-score column softmax + landmark compression
    colstats<<<64, 256>>>();
    compress<<<64, 256>>>();

    // landmark layernorm (g_s, b_s)
    ln_small<<<BATCH*LLC, 256>>>(Kcp, gs, bs);
    ln_small<<<BATCH*LLC, 256>>>(Vcp, gs, bs);

    // fused compressed + windowed attention
    attn<<<dim3(NGRP, NH, BATCH), 128>>>();

    // output projection, scattered back to (SEQ, B, DIM)
    sgemm<1><<<dim3(8,128), 256>>>(Cp, Wo, bo, out, DIMN, 1.f);
}

// round 3
// speedup vs baseline: 1.2104x; 1.2104x over previous
#include <cuda_runtime.h>
#include <math.h>

#define SEQ   4096
#define BATCH 4
#define DIMN  1024
#define NH    16
#define DHD   64
#define LLC   32
#define WWIN  8
#define EEXT  4
#define NGRP  512
#define MROWS (SEQ*BATCH)   // 16384
#define HL    512           // H*L
#define NCH   16            // compress seq-splits
#define NCS   8             // colstats seq-splits
#define KCN   (BATCH*NH*LLC*DHD)   // 131072

// ---------------- scratch (device globals: allocation-free) ----------------
__device__ float g_Q[(size_t)MROWS*DIMN];
__device__ float g_K[(size_t)MROWS*DIMN];
__device__ float g_V[(size_t)MROWS*DIMN];
__device__ float g_D[(size_t)MROWS*HL];
__device__ float g_cmax[BATCH*HL];
__device__ float g_cinv[BATCH*HL];
__device__ float g_Kc[KCN];
__device__ float g_Vc[KCN];
__device__ float g_C[(size_t)MROWS*DIMN];
__device__ float g_pKc[NCH][KCN];
__device__ float g_pVc[NCH][KCN];
__device__ float g_pm[NCS][BATCH*HL];
__device__ float g_ps[NCS][BATCH*HL];

// ---------------- fp32 GEMM inner compute: packed f32x2 FFMA ----------------
__device__ __forceinline__ void sg_compute(
    const float (*As8)[128], const float (*Bs8)[128],
    unsigned long long acc2[8][4], int ty, int tx)
{
    #pragma unroll
    for (int kk=0;kk<8;kk++){
        float ar[8];
        *(float4*)&ar[0] = *(const float4*)&As8[kk][ty*8];
        *(float4*)&ar[4] = *(const float4*)&As8[kk][ty*8+4];
        unsigned long long b2[4];
        const unsigned long long* bp =
            (const unsigned long long*)&Bs8[kk][tx*8];
        #pragma unroll
        for (int j=0;j<4;j++) b2[j] = bp[j];
        #pragma unroll
        for (int i=0;i<8;i++){
            unsigned long long a2;
            asm("mov.b64 %0, {%1, %1};" : "=l"(a2) : "f"(ar[i]));
            #pragma unroll
            for (int j=0;j<4;j++)
                asm("fma.rn.f32x2 %0, %1, %2, %0;"
                    : "+l"(acc2[i][j]) : "l"(a2), "l"(b2[j]));
        }
    }
}

// C = alpha*(A@B + bias). M=16384, K=1024 fixed.
// MODE 0: A rows in (S,B,DIM) layout, C plain. MODE 1: A plain, C scattered.
template<int MODE>
__global__ __launch_bounds__(256) void sgemm(
    const float* __restrict__ A, const float* __restrict__ Bw,
    const float* __restrict__ bias, float* __restrict__ Cout,
    int N, float alpha)
{
    __shared__ float As[2][8][128];
    __shared__ float Bs[2][8][128];

    const int tid = threadIdx.x;
    const int bx = blockIdx.x, by = blockIdx.y;

    const int arow = tid >> 1;
    const int acol = (tid & 1) << 2;
    const int gr = by*128 + arow;
    const float* Aptr;
    if (MODE == 0) {
        int bb = gr >> 12, ss = gr & 4095;
        Aptr = A + ((size_t)(ss*BATCH + bb))*DIMN + acol;
    } else {
        Aptr = A + (size_t)gr*DIMN + acol;
    }
    const int brow = tid >> 5;
    const int bcol = (tid & 31) << 2;
    const float* Bptr = Bw + (size_t)brow*N + bx*128 + bcol;

    unsigned long long acc2[8][4];
    #pragma unroll
    for (int i=0;i<8;i++)
        #pragma unroll
        for (int j=0;j<4;j++) acc2[i][j] = 0ull;

    const int tx = tid & 15, ty = tid >> 4;

    // prime buffer 0
    {
        float4 av = *(const float4*)(Aptr);
        As[0][acol+0][arow]=av.x; As[0][acol+1][arow]=av.y;
        As[0][acol+2][arow]=av.z; As[0][acol+3][arow]=av.w;
        *(float4*)&Bs[0][brow][bcol] = *(const float4*)(Bptr);
    }
    __syncthreads();

    int buf = 0;
    for (int k0 = 8; k0 < DIMN; k0 += 8) {
        float4 av = *(const float4*)(Aptr + k0);
        float4 bv = *(const float4*)(Bptr + (size_t)k0*N);
        sg_compute(As[buf], Bs[buf], acc2, ty, tx);
        int nb = buf ^ 1;
        As[nb][acol+0][arow]=av.x; As[nb][acol+1][arow]=av.y;
        As[nb][acol+2][arow]=av.z; As[nb][acol+3][arow]=av.w;
        *(float4*)&Bs[nb][brow][bcol] = bv;
        __syncthreads();
        buf = nb;
    }
    sg_compute(As[buf], Bs[buf], acc2, ty, tx);

    #pragma unroll
    for (int i=0;i<8;i++){
        int rr = by*128 + ty*8 + i;
        size_t outbase;
        if (MODE == 0) outbase = (size_t)rr*N;
        else { int bb = rr>>12, ss = rr&4095; outbase = ((size_t)(ss*BATCH+bb))*DIMN; }
        #pragma unroll
        for (int j=0;j<4;j++){
            float lo, hi;
            asm("mov.b64 {%0, %1}, %2;" : "=f"(lo), "=f"(hi) : "l"(acc2[i][j]));
            int n = bx*128 + tx*8 + j*2;
            Cout[outbase + n]   = alpha*(lo + bias[n]);
            Cout[outbase + n+1] = alpha*(hi + bias[n+1]);
        }
    }
}

// ---------------- row layernorm over DIM=1024 (in-place) ----------------
__global__ __launch_bounds__(256) void ln_rows(
    float* __restrict__ X, const float* __restrict__ gamma,
    const float* __restrict__ beta)
{
    int row = blockIdx.x;
    float* p = X + (size_t)row*DIMN;
    int tid = threadIdx.x;
    float4 v = *(float4*)(p + tid*4);
    float s  = v.x+v.y+v.z+v.w;
    float s2 = v.x*v.x+v.y*v.y+v.z*v.z+v.w*v.w;
    #pragma unroll
    for (int o=16;o>0;o>>=1){
        s  += __shfl_down_sync(0xffffffffu, s,  o);
        s2 += __shfl_down_sync(0xffffffffu, s2, o);
    }
    __shared__ float rs[8], rs2[8];
    int warp = tid>>5, lane = tid&31;
    if (lane==0){ rs[warp]=s; rs2[warp]=s2; }
    __syncthreads();
    if (tid==0){
        float S=0.f,S2=0.f;
        for(int i=0;i<8;i++){S+=rs[i];S2+=rs2[i];}
        float mean = S*(1.f/DIMN);
        float var  = S2*(1.f/DIMN) - mean*mean;
        rs[0]=mean; rs2[0]=rsqrtf(var + 1e-5f);
    }
    __syncthreads();
    float mean = rs[0], rstd = rs2[0];
    float4 g4 = *(const float4*)(gamma + tid*4);
    float4 b4 = *(const float4*)(beta  + tid*4);
    v.x = (v.x-mean)*rstd*g4.x + b4.x;
    v.y = (v.y-mean)*rstd*g4.y + b4.y;
    v.z = (v.z-mean)*rstd*g4.z + b4.z;
    v.w = (v.w-mean)*rstd*g4.w + b4.w;
    *(float4*)(p + tid*4) = v;
}

// ------- column softmax stats, split over sequence (partials) -------
__global__ __launch_bounds__(256) void colstats_part()
{
    int b  = blockIdx.x >> 4;
    int c0 = (blockIdx.x & 15) << 5;
    int sp = blockIdx.y;                 // 0..NCS-1, 512 rows each
    int cl = threadIdx.x & 31;
    int si = threadIdx.x >> 5;           // 0..7
    int c = c0 + cl;
    int sbeg = sp*(SEQ/NCS), send = sbeg + SEQ/NCS;
    float m = -1e30f, sum = 0.f;
    for (int s = sbeg + si; s < send; s += 8){
        float v = g_D[((size_t)(b*SEQ + s))*HL + c];
        if (v > m){ sum *= __expf(m - v); m = v; }
        sum += __expf(v - m);
    }
    __shared__ float sm[8][32], ss[8][32];
    sm[si][cl]=m; ss[si][cl]=sum;
    __syncthreads();
    if (si == 0){
        float M = sm[0][cl];
        #pragma unroll
        for (int k=1;k<8;k++) M = fmaxf(M, sm[k][cl]);
        float S = 0.f;
        #pragma unroll
        for (int k=0;k<8;k++) S += ss[k][cl]*__expf(sm[k][cl]-M);
        g_pm[sp][b*HL + c] = M;
        g_ps[sp][b*HL + c] = S;
    }
}

__global__ __launch_bounds__(256) void colstats_reduce()
{
    int i = blockIdx.x*256 + threadIdx.x;   // 0..2047
    float M = g_pm[0][i];
    #pragma unroll
    for (int k=1;k<NCS;k++) M = fmaxf(M, g_pm[k][i]);
    float S = 0.f;
    #pragma unroll
    for (int k=0;k<NCS;k++) S += g_ps[k][i]*__expf(g_pm[k][i]-M);
    g_cmax[i] = M;
    g_cinv[i] = 1.f/S;
}

// ----- compressed landmarks, split over sequence (partials) -----
__global__ __launch_bounds__(256) void compress_part()
{
    int b = blockIdx.x >> 4;
    int h = blockIdx.x & 15;
    int ch = blockIdx.y;                  // 0..NCH-1
    int tid = threadIdx.x;
    int d  = tid & 63;
    int lg = tid >> 6;
    __shared__ float wsh[8][32];
    __shared__ float ksh[8][64];
    __shared__ float vsh[8][64];
    __shared__ float msh[32], ish[32];
    if (tid < 32){
        msh[tid] = g_cmax[b*HL + h*32 + tid];
        ish[tid] = g_cinv[b*HL + h*32 + tid];
    }
    __syncthreads();
    float kacc[8], vacc[8];
    #pragma unroll
    for (int i=0;i<8;i++){ kacc[i]=0.f; vacc[i]=0.f; }

    int sbeg = ch*(SEQ/NCH), send = sbeg + SEQ/NCH;
    for (int s0=sbeg; s0<send; s0+=8){
        {
            int si = tid >> 5, l = tid & 31;
            float dv = g_D[((size_t)(b*SEQ + s0 + si))*HL + h*32 + l];
            wsh[si][l] = __expf(dv - msh[l]) * ish[l];
        }
        #pragma unroll
        for (int r=0;r<2;r++){
            int e = tid + r*256;
            int si = e >> 6, dd = e & 63;
            size_t off = ((size_t)(b*SEQ + s0 + si))*DIMN + h*64 + dd;
            ksh[si][dd] = g_K[off];
            vsh[si][dd] = g_V[off];
        }
        __syncthreads();
        #pragma unroll
        for (int si=0; si<8; si++){
            float kv = ksh[si][d], vv = vsh[si][d];
            #pragma unroll
            for (int i=0;i<8;i++){
                float w = wsh[si][lg*8+i];
                kacc[i] += w*kv; vacc[i] += w*vv;
            }
        }
        __syncthreads();
    }
    #pragma unroll
    for (int i=0;i<8;i++){
        int l = lg*8+i;
        size_t off = (((size_t)(b*NH+h))*LLC + l)*DHD + d;
        g_pKc[ch][off] = kacc[i];
        g_pVc[ch][off] = vacc[i];
    }
}

__global__ __launch_bounds__(256) void compress_reduce()
{
    int i = blockIdx.x*256 + threadIdx.x;   // 0..KCN-1
    float sk = 0.f, sv = 0.f;
    #pragma unroll
    for (int c=0;c<NCH;c++){ sk += g_pKc[c][i]; sv += g_pVc[c][i]; }
    g_Kc[i] = sk;
    g_Vc[i] = sv;
}

// ---- layernorm of Kc/Vc over (h,d) for each (b,l) ----
__global__ __launch_bounds__(256) void ln_small(
    float* __restrict__ X, const float* __restrict__ gamma,
    const float* __restrict__ beta)
{
    int b = blockIdx.x >> 5;
    int l = blockIdx.x & 31;
    int tid = threadIdx.x;
    float vals[4];
    float s=0.f, s2=0.f;
    #pragma unroll
    for (int k=0;k<4;k++){
        int e = tid + k*256;
        int h = e >> 6, dd = e & 63;
        float v = X[(((size_t)(b*NH+h))*LLC + l)*DHD + dd];
        vals[k]=v; s+=v; s2+=v*v;
    }
    #pragma unroll
    for (int o=16;o>0;o>>=1){
        s  += __shfl_down_sync(0xffffffffu, s,  o);
        s2 += __shfl_down_sync(0xffffffffu, s2, o);
    }
    __shared__ float rs[8], rs2[8];
    int warp = tid>>5, lane = tid&31;
    if (lane==0){ rs[warp]=s; rs2[warp]=s2; }
    __syncthreads();
    if (tid==0){
        float S=0.f,S2=0.f;
        for(int i=0;i<8;i++){S+=rs[i];S2+=rs2[i];}
        float mean = S*(1.f/DIMN);
        float var  = S2*(1.f/DIMN) - mean*mean;
        rs[0]=mean; rs2[0]=rsqrtf(var + 1e-5f);
    }
    __syncthreads();
    float mean = rs[0], rstd = rs2[0];
    #pragma unroll
    for (int k=0;k<4;k++){
        int e = tid + k*256;
        int h = e >> 6, dd = e & 63;
        X[(((size_t)(b*NH+h))*LLC + l)*DHD + dd] =
            (vals[k]-mean)*rstd*gamma[e] + beta[e];
    }
}

// ---------------- fused attention: 32 compressed + 16 window keys ----------------
#define PADW 68
__global__ __launch_bounds__(128) void attn()
{
    int g = blockIdx.x, h = blockIdx.y, b = blockIdx.z;
    __shared__ float qsh[8][PADW];
    __shared__ float kc[32][PADW];
    __shared__ float vc[32][PADW];
    __shared__ float kt[16][PADW];
    __shared__ float vt[16][PADW];
    __shared__ float logit[8][48];
    __shared__ float prob[8][48];
    int tid = threadIdx.x;

    {   // Q tile: 8 x 64
        int w = tid>>4, c=(tid&15)<<2;
        *(float4*)&qsh[w][c] =
            *(const float4*)&g_Q[((size_t)(b*SEQ + g*8 + w))*DIMN + h*64 + c];
    }
    #pragma unroll
    for (int r=0;r<4;r++){   // Kc/Vc: 32 x 64 each
        int e = tid + r*128;
        int l = e>>4, c=(e&15)<<2;
        size_t off = (((size_t)(b*NH+h))*LLC + l)*DHD + c;
        *(float4*)&kc[l][c] = *(const float4*)&g_Kc[off];
        *(float4*)&vc[l][c] = *(const float4*)&g_Vc[off];
    }
    #pragma unroll
    for (int r=0;r<2;r++){   // window tiles: 16 x 64
        int e = tid + r*128;
        int j = e>>4, c=(e&15)<<2;
        int pos = g*WWIN - EEXT + j;
        float4 kz = make_float4(0,0,0,0), vz = make_float4(0,0,0,0);
        if (pos >= 0 && pos < SEQ){
            size_t off = ((size_t)(b*SEQ+pos))*DIMN + h*64 + c;
            kz = *(const float4*)&g_K[off];
            vz = *(const float4*)&g_V[off];
        }
        *(float4*)&kt[j][c] = kz;
        *(float4*)&vt[j][c] = vz;
    }
    __syncthreads();

    #pragma unroll
    for (int r=0;r<3;r++){   // 384 dots of length 64
        int t = tid + r*128;
        int w = t/48, j = t%48;
        float acc = 0.f;
        const float* kp = (j<32) ? &kc[j][0] : &kt[j-32][0];
        #pragma unroll
        for (int c=0;c<64;c++) acc += qsh[w][c]*kp[c];
        if (j>=32){
            int pos = g*WWIN - EEXT + (j-32);
            if (pos < 0 || pos >= SEQ) acc = -1e30f;
        }
        logit[w][j] = acc;
    }
    __syncthreads();

    if (tid < 8){
        int w = tid;
        float m = -1e30f;
        for (int j=0;j<48;j++) m = fmaxf(m, logit[w][j]);
        float ssum = 0.f;
        for (int j=0;j<48;j++){ float p = __expf(logit[w][j]-m); prob[w][j]=p; ssum+=p; }
        float inv = 1.f/ssum;
        for (int j=0;j<48;j++) prob[w][j] *= inv;
    }
    __syncthreads();

    #pragma unroll
    for (int r=0;r<4;r++){   // 8 x 64 outputs
        int t = tid + r*128;
        int w = t>>6, dd = t&63;
        float acc = 0.f;
        #pragma unroll
        for (int j=0;j<32;j++) acc += prob[w][j]*vc[j][dd];
        #pragma unroll
        for (int j=0;j<16;j++) acc += prob[w][32+j]*vt[j][dd];
        g_C[((size_t)(b*SEQ + g*8 + w))*DIMN + h*64 + dd] = acc;
    }
}

// ---------------- launch ----------------
extern "C" void kernel_launch(void* const* d_in, const int* in_sizes, int n_in,
                              void* d_out, int out_size)
{
    const float* query = (const float*)d_in[0];
    const float* Wq = (const float*)d_in[1];
    const float* bq = (const float*)d_in[2];
    const float* Wk = (const float*)d_in[3];
    const float* bk = (const float*)d_in[4];
    const float* Wv = (const float*)d_in[5];
    const float* bv = (const float*)d_in[6];
    const float* Wo = (const float*)d_in[7];
    const float* bo = (const float*)d_in[8];
    const float* gl = (const float*)d_in[9];
    const float* bl = (const float*)d_in[10];
    const float* gs = (const float*)d_in[11];
    const float* bs = (const float*)d_in[12];
    const float* Wd = (const float*)d_in[13];
    const float* bd = (const float*)d_in[14];
    float* out = (float*)d_out;

    float *Qp, *Kp, *Vp, *Dp, *Cp, *Kcp, *Vcp;
    cudaGetSymbolAddress((void**)&Qp,  g_Q);
    cudaGetSymbolAddress((void**)&Kp,  g_K);
    cudaGetSymbolAddress((void**)&Vp,  g_V);
    cudaGetSymbolAddress((void**)&Dp,  g_D);
    cudaGetSymbolAddress((void**)&Cp,  g_C);
    cudaGetSymbolAddress((void**)&Kcp, g_Kc);
    cudaGetSymbolAddress((void**)&Vcp, g_Vc);

    // projections
    sgemm<0><<<dim3(8,128), 256>>>(query, Wq, bq, Qp, DIMN, 0.125f);
    sgemm<0><<<dim3(8,128), 256>>>(query, Wk, bk, Kp, DIMN, 1.f);
    sgemm<0><<<dim3(8,128), 256>>>(query, Wv, bv, Vp, DIMN, 1.f);
    sgemm<0><<<dim3(4,128), 256>>>(query, Wd, bd, Dp, HL,   1.f);

    // K/V layernorm (g_l, b_l)
    ln_rows<<<MROWS, 256>>>(Kp, gl, bl);
    ln_rows<<<MROWS, 256>>>(Vp, gl, bl);

    // head-score column softmax (split + reduce)
    colstats_part<<<dim3(64, NCS), 256>>>();
    colstats_reduce<<<8, 256>>>();

    // landmark compression (split + reduce)
    compress_part<<<dim3(64, NCH), 256>>>();
    compress_reduce<<<KCN/256, 256>>>();

    // landmark layernorm (g_s, b_s)
    ln_small<<<BATCH*LLC, 256>>>(Kcp, gs, bs);
    ln_small<<<BATCH*LLC, 256>>>(Vcp, gs, bs);

    // fused compressed + windowed attention
    attn<<<dim3(NGRP, NH, BATCH), 128>>>();

    // output projection, scattered back to (SEQ, B, DIM)
    sgemm<1><<<dim3(8,128), 256>>>(Cp, Wo, bo, out, DIMN, 1.f);
}

// round 8
// speedup vs baseline: 2.1704x; 1.7930x over previous
#include <cuda_runtime.h>
#include <math.h>
#include <stdint.h>

#define SEQ   4096
#define BATCH 4
#define DIMN  1024
#define NH    16
#define DHD   64
#define LLC   32
#define WWIN  8
#define EEXT  4
#define NGRP  512
#define MROWS (SEQ*BATCH)   // 16384
#define HL    512           // H*L
#define NCH   16            // compress seq-splits
#define NCS   8             // colstats seq-splits
#define KCN   (BATCH*NH*LLC*DHD)   // 131072

// ---------------- scratch (device globals: allocation-free) ----------------
__device__ float g_Q[(size_t)MROWS*DIMN];
__device__ float g_K[(size_t)MROWS*DIMN];
__device__ float g_V[(size_t)MROWS*DIMN];
__device__ float g_D[(size_t)MROWS*HL];
__device__ float g_cmax[BATCH*HL];
__device__ float g_cinv[BATCH*HL];
__device__ float g_Kc[KCN];
__device__ float g_Vc[KCN];
__device__ float g_C[(size_t)MROWS*DIMN];
__device__ float g_pKc[NCH][KCN];
__device__ float g_pVc[NCH][KCN];
__device__ float g_pm[NCS][BATCH*HL];
__device__ float g_ps[NCS][BATCH*HL];

__device__ __forceinline__ float to_tf32(float x){
    float r; asm("cvt.rna.tf32.f32 %0, %1;" : "=f"(r) : "f"(x)); return r;
}
__device__ __forceinline__ void mma_tf32_16n8k8(
    float* c, const uint32_t* a, const uint32_t* b)
{
    asm volatile(
        "mma.sync.aligned.m16n8k8.row.col.f32.tf32.tf32.f32 "
        "{%0,%1,%2,%3}, {%4,%5,%6,%7}, {%8,%9}, {%0,%1,%2,%3};"
        : "+f"(c[0]), "+f"(c[1]), "+f"(c[2]), "+f"(c[3])
        : "r"(a[0]), "r"(a[1]), "r"(a[2]), "r"(a[3]),
          "r"(b[0]), "r"(b[1]));
}

// ---------------- tf32 HMMA GEMM: C = alpha*(A@W + bias) ----------------
// M=16384, K=1024 fixed. CTA tile 128x128, 8 warps (2m x 4n), warp tile 64x32.
// K-chunk 32, double-buffered smem, 1 sync/chunk.
// MODE 0: A rows gathered from (S,B,DIM); MODE 1: A plain, C scattered back.
#define APAD 36
#define BPAD 136
#define ASTRIDE (128*APAD)      // floats per A buffer
#define BSTRIDE (32*BPAD)       // floats per B buffer
#define GM_SMEM ((2*ASTRIDE + 2*BSTRIDE)*4)   // 71680 bytes

template<int MODE>
__global__ __launch_bounds__(256) void gemm_mma(
    const float* __restrict__ A, const float* __restrict__ W,
    const float* __restrict__ bias, float* __restrict__ Cout,
    int N, float alpha)
{
    extern __shared__ float sh[];
    float* Asm = sh;                 // [2][128][APAD]
    float* Bsm = sh + 2*ASTRIDE;     // [2][32][BPAD]

    const int tid  = threadIdx.x;
    const int lane = tid & 31, warp = tid >> 5;
    const int wm = warp & 1, wn = warp >> 1;       // 2 x 4 warp grid
    const int g = lane >> 2, tig = lane & 3;
    const int m0 = blockIdx.y*128, n0 = blockIdx.x*128;

    // A loader: 2 threads per row, 16 floats each
    const int ar = tid >> 1, ak = (tid & 1)*16;
    const float* aptr;
    {
        int gr = m0 + ar;
        if (MODE == 0){ int bb = gr >> 12, ss = gr & 4095;
            aptr = A + (size_t)(ss*BATCH + bb)*DIMN + ak; }
        else aptr = A + (size_t)gr*DIMN + ak;
    }
    // B loader: 8 threads per k-row, 16 floats each
    const int br = tid >> 3, bn = (tid & 7)*16;
    const float* bptr = W + (size_t)br*N + n0 + bn;

    float acc[4][4][4];
    #pragma unroll
    for (int i=0;i<4;i++)
        #pragma unroll
        for (int j=0;j<4;j++)
            #pragma unroll
            for (int k=0;k<4;k++) acc[i][j][k]=0.f;

    // ---- prime buffer 0 ----
    {
        float* Ad = Asm;  float* Bd = Bsm;
        #pragma unroll
        for (int i=0;i<4;i++){
            float4 v = *(const float4*)(aptr + i*4);
            float* p = Ad + ar*APAD + ak + i*4;
            p[0]=to_tf32(v.x); p[1]=to_tf32(v.y);
            p[2]=to_tf32(v.z); p[3]=to_tf32(v.w);
        }
        #pragma unroll
        for (int i=0;i<4;i++){
            float4 v = *(const float4*)(bptr + i*4);
            float* p = Bd + br*BPAD + bn + i*4;
            p[0]=to_tf32(v.x); p[1]=to_tf32(v.y);
            p[2]=to_tf32(v.z); p[3]=to_tf32(v.w);
        }
    }
    __syncthreads();

    int buf = 0;
    for (int c = 1; c <= 32; c++){
        float4 av[4], bv[4];
        if (c < 32){
            const int k0 = c*32;
            #pragma unroll
            for (int i=0;i<4;i++) av[i] = *(const float4*)(aptr + k0 + i*4);
            #pragma unroll
            for (int i=0;i<4;i++) bv[i] = *(const float4*)(bptr + (size_t)k0*N + i*4);
        }
        // ---- compute on buf ----
        {
            const uint32_t* Ad = (const uint32_t*)(Asm + buf*ASTRIDE);
            const uint32_t* Bd = (const uint32_t*)(Bsm + buf*BSTRIDE);
            #pragma unroll
            for (int kk=0;kk<4;kk++){
                uint32_t af[4][4];
                #pragma unroll
                for (int fm=0;fm<4;fm++){
                    const uint32_t* ap = Ad + (wm*64 + fm*16)*APAD + kk*8;
                    af[fm][0] = ap[g*APAD + tig];
                    af[fm][1] = ap[(g+8)*APAD + tig];
                    af[fm][2] = ap[g*APAD + tig + 4];
                    af[fm][3] = ap[(g+8)*APAD + tig + 4];
                }
                uint32_t bf[4][2];
                #pragma unroll
                for (int fn=0;fn<4;fn++){
                    const uint32_t* bp = Bd + (kk*8)*BPAD + wn*32 + fn*8 + g;
                    bf[fn][0] = bp[tig*BPAD];
                    bf[fn][1] = bp[(tig+4)*BPAD];
                }
                #pragma unroll
                for (int fm=0;fm<4;fm++)
                    #pragma unroll
                    for (int fn=0;fn<4;fn++)
                        mma_tf32_16n8k8(acc[fm][fn], af[fm], bf[fn]);
            }
        }
        if (c < 32){
            float* Ad = Asm + (buf^1)*ASTRIDE;
            float* Bd = Bsm + (buf^1)*BSTRIDE;
            #pragma unroll
            for (int i=0;i<4;i++){
                float* p = Ad + ar*APAD + ak + i*4;
                p[0]=to_tf32(av[i].x); p[1]=to_tf32(av[i].y);
                p[2]=to_tf32(av[i].z); p[3]=to_tf32(av[i].w);
            }
            #pragma unroll
            for (int i=0;i<4;i++){
                float* p = Bd + br*BPAD + bn + i*4;
                p[0]=to_tf32(bv[i].x); p[1]=to_tf32(bv[i].y);
                p[2]=to_tf32(bv[i].z); p[3]=to_tf32(bv[i].w);
            }
            __syncthreads();
            buf ^= 1;
        }
    }

    // ---- epilogue ----
    #pragma unroll
    for (int fm=0;fm<4;fm++){
        int r0 = m0 + wm*64 + fm*16 + g;
        int r1 = r0 + 8;
        size_t ob0, ob1;
        if (MODE == 0){ ob0 = (size_t)r0*N; ob1 = (size_t)r1*N; }
        else {
            int bb0 = r0>>12, ss0 = r0&4095;
            int bb1 = r1>>12, ss1 = r1&4095;
            ob0 = (size_t)(ss0*BATCH+bb0)*DIMN;
            ob1 = (size_t)(ss1*BATCH+bb1)*DIMN;
        }
        #pragma unroll
        for (int fn=0;fn<4;fn++){
            int col = n0 + wn*32 + fn*8 + tig*2;
            float b0 = bias[col], b1 = bias[col+1];
            float2 v0 = make_float2(alpha*(acc[fm][fn][0]+b0),
                                    alpha*(acc[fm][fn][1]+b1));
            float2 v1 = make_float2(alpha*(acc[fm][fn][2]+b0),
                                    alpha*(acc[fm][fn][3]+b1));
            *(float2*)&Cout[ob0 + col] = v0;
            *(float2*)&Cout[ob1 + col] = v1;
        }
    }
}

// ---------------- row layernorm over DIM=1024 (in-place) ----------------
__global__ __launch_bounds__(256) void ln_rows(
    float* __restrict__ X, const float* __restrict__ gamma,
    const float* __restrict__ beta)
{
    int row = blockIdx.x;
    float* p = X + (size_t)row*DIMN;
    int tid = threadIdx.x;
    float4 v = *(float4*)(p + tid*4);
    float s  = v.x+v.y+v.z+v.w;
    float s2 = v.x*v.x+v.y*v.y+v.z*v.z+v.w*v.w;
    #pragma unroll
    for (int o=16;o>0;o>>=1){
        s  += __shfl_down_sync(0xffffffffu, s,  o);
        s2 += __shfl_down_sync(0xffffffffu, s2, o);
    }
    __shared__ float rs[8], rs2[8];
    int warp = tid>>5, lane = tid&31;
    if (lane==0){ rs[warp]=s; rs2[warp]=s2; }
    __syncthreads();
    if (tid==0){
        float S=0.f,S2=0.f;
        for(int i=0;i<8;i++){S+=rs[i];S2+=rs2[i];}
        float mean = S*(1.f/DIMN);
        float var  = S2*(1.f/DIMN) - mean*mean;
        rs[0]=mean; rs2[0]=rsqrtf(var + 1e-5f);
    }
    __syncthreads();
    float mean = rs[0], rstd = rs2[0];
    float4 g4 = *(const float4*)(gamma + tid*4);
    float4 b4 = *(const float4*)(beta  + tid*4);
    v.x = (v.x-mean)*rstd*g4.x + b4.x;
    v.y = (v.y-mean)*rstd*g4.y + b4.y;
    v.z = (v.z-mean)*rstd*g4.z + b4.z;
    v.w = (v.w-mean)*rstd*g4.w + b4.w;
    *(float4*)(p + tid*4) = v;
}

// ------- column softmax stats, split over sequence (partials) -------
__global__ __launch_bounds__(256) void colstats_part()
{
    int b  = blockIdx.x >> 4;
    int c0 = (blockIdx.x & 15) << 5;
    int sp = blockIdx.y;
    int cl = threadIdx.x & 31;
    int si = threadIdx.x >> 5;
    int c = c0 + cl;
    int sbeg = sp*(SEQ/NCS), send = sbeg + SEQ/NCS;
    float m = -1e30f, sum = 0.f;
    for (int s = sbeg + si; s < send; s += 8){
        float v = g_D[((size_t)(b*SEQ + s))*HL + c];
        if (v > m){ sum *= __expf(m - v); m = v; }
        sum += __expf(v - m);
    }
    __shared__ float sm[8][32], ss[8][32];
    sm[si][cl]=m; ss[si][cl]=sum;
    __syncthreads();
    if (si == 0){
        float M = sm[0][cl];
        #pragma unroll
        for (int k=1;k<8;k++) M = fmaxf(M, sm[k][cl]);
        float S = 0.f;
        #pragma unroll
        for (int k=0;k<8;k++) S += ss[k][cl]*__expf(sm[k][cl]-M);
        g_pm[sp][b*HL + c] = M;
        g_ps[sp][b*HL + c] = S;
    }
}

__global__ __launch_bounds__(256) void colstats_reduce()
{
    int i = blockIdx.x*256 + threadIdx.x;
    float M = g_pm[0][i];
    #pragma unroll
    for (int k=1;k<NCS;k++) M = fmaxf(M, g_pm[k][i]);
    float S = 0.f;
    #pragma unroll
    for (int k=0;k<NCS;k++) S += g_ps[k][i]*__expf(g_pm[k][i]-M);
    g_cmax[i] = M;
    g_cinv[i] = 1.f/S;
}

// ----- compressed landmarks, split over sequence (partials) -----
__global__ __launch_bounds__(256) void compress_part()
{
    int b = blockIdx.x >> 4;
    int h = blockIdx.x & 15;
    int ch = blockIdx.y;
    int tid = threadIdx.x;
    int d  = tid & 63;
    int lg = tid >> 6;
    __shared__ float wsh[8][32];
    __shared__ float ksh[8][64];
    __shared__ float vsh[8][64];
    __shared__ float msh[32], ish[32];
    if (tid < 32){
        msh[tid] = g_cmax[b*HL + h*32 + tid];
        ish[tid] = g_cinv[b*HL + h*32 + tid];
    }
    __syncthreads();
    float kacc[8], vacc[8];
    #pragma unroll
    for (int i=0;i<8;i++){ kacc[i]=0.f; vacc[i]=0.f; }

    int sbeg = ch*(SEQ/NCH), send = sbeg + SEQ/NCH;
    for (int s0=sbeg; s0<send; s0+=8){
        {
            int si = tid >> 5, l = tid & 31;
            float dv = g_D[((size_t)(b*SEQ + s0 + si))*HL + h*32 + l];
            wsh[si][l] = __expf(dv - msh[l]) * ish[l];
        }
        #pragma unroll
        for (int r=0;r<2;r++){
            int e = tid + r*256;
            int si = e >> 6, dd = e & 63;
            size_t off = ((size_t)(b*SEQ + s0 + si))*DIMN + h*64 + dd;
            ksh[si][dd] = g_K[off];
            vsh[si][dd] = g_V[off];
        }
        __syncthreads();
        #pragma unroll
        for (int si=0; si<8; si++){
            float kv = ksh[si][d], vv = vsh[si][d];
            #pragma unroll
            for (int i=0;i<8;i++){
                float w = wsh[si][lg*8+i];
                kacc[i] += w*kv; vacc[i] += w*vv;
            }
        }
        __syncthreads();
    }
    #pragma unroll
    for (int i=0;i<8;i++){
        int l = lg*8+i;
        size_t off = (((size_t)(b*NH+h))*LLC + l)*DHD + d;
        g_pKc[ch][off] = kacc[i];
        g_pVc[ch][off] = vacc[i];
    }
}

__global__ __launch_bounds__(256) void compress_reduce()
{
    int i = blockIdx.x*256 + threadIdx.x;
    float sk = 0.f, sv = 0.f;
    #pragma unroll
    for (int c=0;c<NCH;c++){ sk += g_pKc[c][i]; sv += g_pVc[c][i]; }
    g_Kc[i] = sk;
    g_Vc[i] = sv;
}

// ---- layernorm of Kc/Vc over (h,d) for each (b,l) ----
__global__ __launch_bounds__(256) void ln_small(
    float* __restrict__ X, const float* __restrict__ gamma,
    const float* __restrict__ beta)
{
    int b = blockIdx.x >> 5;
    int l = blockIdx.x & 31;
    int tid = threadIdx.x;
    float vals[4];
    float s=0.f, s2=0.f;
    #pragma unroll
    for (int k=0;k<4;k++){
        int e = tid + k*256;
        int h = e >> 6, dd = e & 63;
        float v = X[(((size_t)(b*NH+h))*LLC + l)*DHD + dd];
        vals[k]=v; s+=v; s2+=v*v;
    }
    #pragma unroll
    for (int o=16;o>0;o>>=1){
        s  += __shfl_down_sync(0xffffffffu, s,  o);
        s2 += __shfl_down_sync(0xffffffffu, s2, o);
    }
    __shared__ float rs[8], rs2[8];
    int warp = tid>>5, lane = tid&31;
    if (lane==0){ rs[warp]=s; rs2[warp]=s2; }
    __syncthreads();
    if (tid==0){
        float S=0.f,S2=0.f;
        for(int i=0;i<8;i++){S+=rs[i];S2+=rs2[i];}
        float mean = S*(1.f/DIMN);
        float var  = S2*(1.f/DIMN) - mean*mean;
        rs[0]=mean; rs2[0]=rsqrtf(var + 1e-5f);
    }
    __syncthreads();
    float mean = rs[0], rstd = rs2[0];
    #pragma unroll
    for (int k=0;k<4;k++){
        int e = tid + k*256;
        int h = e >> 6, dd = e & 63;
        X[(((size_t)(b*NH+h))*LLC + l)*DHD + dd] =
            (vals[k]-mean)*rstd*gamma[e] + beta[e];
    }
}

// ---------------- fused attention: 32 compressed + 16 window keys ----------------
#define PADW 68
__global__ __launch_bounds__(128) void attn()
{
    int g = blockIdx.x, h = blockIdx.y, b = blockIdx.z;
    __shared__ float qsh[8][PADW];
    __shared__ float kc[32][PADW];
    __shared__ float vc[32][PADW];
    __shared__ float kt[16][PADW];
    __shared__ float vt[16][PADW];
    __shared__ float logit[8][48];
    __shared__ float prob[8][48];
    int tid = threadIdx.x;

    {
        int w = tid>>4, c=(tid&15)<<2;
        *(float4*)&qsh[w][c] =
            *(const float4*)&g_Q[((size_t)(b*SEQ + g*8 + w))*DIMN + h*64 + c];
    }
    #pragma unroll
    for (int r=0;r<4;r++){
        int e = tid + r*128;
        int l = e>>4, c=(e&15)<<2;
        size_t off = (((size_t)(b*NH+h))*LLC + l)*DHD + c;
        *(float4*)&kc[l][c] = *(const float4*)&g_Kc[off];
        *(float4*)&vc[l][c] = *(const float4*)&g_Vc[off];
    }
    #pragma unroll
    for (int r=0;r<2;r++){
        int e = tid + r*128;
        int j = e>>4, c=(e&15)<<2;
        int pos = g*WWIN - EEXT + j;
        float4 kz = make_float4(0,0,0,0), vz = make_float4(0,0,0,0);
        if (pos >= 0 && pos < SEQ){
            size_t off = ((size_t)(b*SEQ+pos))*DIMN + h*64 + c;
            kz = *(const float4*)&g_K[off];
            vz = *(const float4*)&g_V[off];
        }
        *(float4*)&kt[j][c] = kz;
        *(float4*)&vt[j][c] = vz;
    }
    __syncthreads();

    #pragma unroll
    for (int r=0;r<3;r++){
        int t = tid + r*128;
        int w = t/48, j = t%48;
        float acc = 0.f;
        const float* kp = (j<32) ? &kc[j][0] : &kt[j-32][0];
        #pragma unroll
        for (int c=0;c<64;c++) acc += qsh[w][c]*kp[c];
        if (j>=32){
            int pos = g*WWIN - EEXT + (j-32);
            if (pos < 0 || pos >= SEQ) acc = -1e30f;
        }
        logit[w][j] = acc;
    }
    __syncthreads();

    if (tid < 8){
        int w = tid;
        float m = -1e30f;
        for (int j=0;j<48;j++) m = fmaxf(m, logit[w][j]);
        float ssum = 0.f;
        for (int j=0;j<48;j++){ float p = __expf(logit[w][j]-m); prob[w][j]=p; ssum+=p; }
        float inv = 1.f/ssum;
        for (int j=0;j<48;j++) prob[w][j] *= inv;
    }
    __syncthreads();

    #pragma unroll
    for (int r=0;r<4;r++){
        int t = tid + r*128;
        int w = t>>6, dd = t&63;
        float acc = 0.f;
        #pragma unroll
        for (int j=0;j<32;j++) acc += prob[w][j]*vc[j][dd];
        #pragma unroll
        for (int j=0;j<16;j++) acc += prob[w][32+j]*vt[j][dd];
        g_C[((size_t)(b*SEQ + g*8 + w))*DIMN + h*64 + dd] = acc;
    }
}

// ---------------- launch ----------------
extern "C" void kernel_launch(void* const* d_in, const int* in_sizes, int n_in,
                              void* d_out, int out_size)
{
    const float* query = (const float*)d_in[0];
    const float* Wq = (const float*)d_in[1];
    const float* bq = (const float*)d_in[2];
    const float* Wk = (const float*)d_in[3];
    const float* bk = (const float*)d_in[4];
    const float* Wv = (const float*)d_in[5];
    const float* bv = (const float*)d_in[6];
    const float* Wo = (const float*)d_in[7];
    const float* bo = (const float*)d_in[8];
    const float* gl = (const float*)d_in[9];
    const float* bl = (const float*)d_in[10];
    const float* gs = (const float*)d_in[11];
    const float* bs = (const float*)d_in[12];
    const float* Wd = (const float*)d_in[13];
    const float* bd = (const float*)d_in[14];
    float* out = (float*)d_out;

    float *Qp, *Kp, *Vp, *Dp, *Cp, *Kcp, *Vcp;
    cudaGetSymbolAddress((void**)&Qp,  g_Q);
    cudaGetSymbolAddress((void**)&Kp,  g_K);
    cudaGetSymbolAddress((void**)&Vp,  g_V);
    cudaGetSymbolAddress((void**)&Dp,  g_D);
    cudaGetSymbolAddress((void**)&Cp,  g_C);
    cudaGetSymbolAddress((void**)&Kcp, g_Kc);
    cudaGetSymbolAddress((void**)&Vcp, g_Vc);

    static int smem_cfg = 0;
    if (!smem_cfg){
        cudaFuncSetAttribute(gemm_mma<0>, cudaFuncAttributeMaxDynamicSharedMemorySize, GM_SMEM);
        cudaFuncSetAttribute(gemm_mma<1>, cudaFuncAttributeMaxDynamicSharedMemorySize, GM_SMEM);
        smem_cfg = 1;
    }

    // projections (tf32 HMMA tensor cores)
    gemm_mma<0><<<dim3(8,128), 256, GM_SMEM>>>(query, Wq, bq, Qp, DIMN, 0.125f);
    gemm_mma<0><<<dim3(8,128), 256, GM_SMEM>>>(query, Wk, bk, Kp, DIMN, 1.f);
    gemm_mma<0><<<dim3(8,128), 256, GM_SMEM>>>(query, Wv, bv, Vp, DIMN, 1.f);
    gemm_mma<0><<<dim3(4,128), 256, GM_SMEM>>>(query, Wd, bd, Dp, HL,   1.f);

    // K/V layernorm (g_l, b_l)
    ln_rows<<<MROWS, 256>>>(Kp, gl, bl);
    ln_rows<<<MROWS, 256>>>(Vp, gl, bl);

    // head-score column softmax (split + reduce)
    colstats_part<<<dim3(64, NCS), 256>>>();
    colstats_reduce<<<8, 256>>>();

    // landmark compression (split + reduce)
    compress_part<<<dim3(64, NCH), 256>>>();
    compress_reduce<<<KCN/256, 256>>>();

    // landmark layernorm (g_s, b_s)
    ln_small<<<BATCH*LLC, 256>>>(Kcp, gs, bs);
    ln_small<<<BATCH*LLC, 256>>>(Vcp, gs, bs);

    // fused compressed + windowed attention
    attn<<<dim3(NGRP, NH, BATCH), 128>>>();

    // output projection, scattered back to (SEQ, B, DIM)
    gemm_mma<1><<<dim3(8,128), 256, GM_SMEM>>>(Cp, Wo, bo, out, DIMN, 1.f);
}

// round 9
// speedup vs baseline: 2.7283x; 1.2571x over previous
#include <cuda_runtime.h>
#include <math.h>
#include <stdint.h>

#define SEQ   4096
#define BATCH 4
#define DIMN  1024
#define NH    16
#define DHD   64
#define LLC   32
#define WWIN  8
#define EEXT  4
#define NGRP  512
#define MROWS (SEQ*BATCH)   // 16384
#define HL    512           // H*L
#define NCH   32            // compress seq-splits
#define NCS   8             // colstats seq-splits
#define KCN   (BATCH*NH*LLC*DHD)   // 131072

// ---------------- scratch (device globals: allocation-free) ----------------
__device__ float g_Q[(size_t)MROWS*DIMN];
__device__ float g_K[(size_t)MROWS*DIMN];
__device__ float g_V[(size_t)MROWS*DIMN];
__device__ float g_D[(size_t)MROWS*HL];
__device__ float g_cmax[BATCH*HL];
__device__ float g_cinv[BATCH*HL];
__device__ float g_Kc[KCN];
__device__ float g_Vc[KCN];
__device__ float g_C[(size_t)MROWS*DIMN];
__device__ float g_pKc[NCH][KCN];
__device__ float g_pVc[NCH][KCN];
__device__ float g_pm[NCS][BATCH*HL];
__device__ float g_ps[NCS][BATCH*HL];

__device__ __forceinline__ float to_tf32(float x){
    float r; asm("cvt.rna.tf32.f32 %0, %1;" : "=f"(r) : "f"(x)); return r;
}
__device__ __forceinline__ uint32_t tf32u(float x){
    return __float_as_uint(to_tf32(x));
}
__device__ __forceinline__ uint32_t smem_u32(const void* p){
    uint32_t a;
    asm("{ .reg .u64 t; cvta.to.shared.u64 t, %1; cvt.u32.u64 %0, t; }"
        : "=r"(a) : "l"(p));
    return a;
}
__device__ __forceinline__ void cpa16(uint32_t s, const float* g){
    asm volatile("cp.async.cg.shared.global [%0], [%1], 16;" :: "r"(s), "l"(g));
}
__device__ __forceinline__ void mma_tf32_16n8k8(
    float* c, const uint32_t* a, const uint32_t* b)
{
    asm volatile(
        "mma.sync.aligned.m16n8k8.row.col.f32.tf32.tf32.f32 "
        "{%0,%1,%2,%3}, {%4,%5,%6,%7}, {%8,%9}, {%0,%1,%2,%3};"
        : "+f"(c[0]), "+f"(c[1]), "+f"(c[2]), "+f"(c[3])
        : "r"(a[0]), "r"(a[1]), "r"(a[2]), "r"(a[3]),
          "r"(b[0]), "r"(b[1]));
}

// ---------------- tf32 HMMA GEMM with cp.async pipeline ----------------
// C = alpha*(A@W + bias). M=16384, K=1024. CTA tile 128x128, 8 warps (2x4),
// warp tile 64x32. K-chunk 16, 4-stage cp.async pipeline.
// MODE 0: A rows gathered from (S,B,DIM); MODE 1: A plain, C scattered back.
#define STAGES 4
#define APAD 20
#define BPAD 136
#define AST (128*APAD)          // floats per A stage (2560)
#define BST (16*BPAD)           // floats per B stage (2176)
#define GM_SMEM (STAGES*(AST+BST)*4)   // 75776 bytes

template<int MODE>
__global__ __launch_bounds__(256, 2) void gemm_mma(
    const float* __restrict__ A, const float* __restrict__ W,
    const float* __restrict__ bias, float* __restrict__ Cout,
    int N, float alpha)
{
    extern __shared__ float sh[];
    float* Asm = sh;
    float* Bsm = sh + STAGES*AST;

    const int tid  = threadIdx.x;
    const int lane = tid & 31, warp = tid >> 5;
    const int wm = warp & 1, wn = warp >> 1;
    const int g = lane >> 2, tig = lane & 3;
    const int m0 = blockIdx.y*128, n0 = blockIdx.x*128;

    // A loader: 2 threads/row, 8 floats each
    const int ar = tid >> 1, ak = (tid & 1)*8;
    const float* aptr;
    {
        int gr = m0 + ar;
        if (MODE == 0){ int bb = gr >> 12, ss = gr & 4095;
            aptr = A + (size_t)(ss*BATCH + bb)*DIMN + ak; }
        else aptr = A + (size_t)gr*DIMN + ak;
    }
    // B loader: 16 threads/row, 8 floats each
    const int br = tid >> 4, bn = (tid & 15)*8;
    const float* bptr = W + (size_t)br*N + n0 + bn;

    const uint32_t aSt = smem_u32(Asm) + (uint32_t)(ar*APAD + ak)*4u;
    const uint32_t bSt = smem_u32(Bsm) + (uint32_t)(br*BPAD + bn)*4u;

    float acc[4][4][4];
    #pragma unroll
    for (int i=0;i<4;i++)
        #pragma unroll
        for (int j=0;j<4;j++)
            #pragma unroll
            for (int k=0;k<4;k++) acc[i][j][k]=0.f;

    #pragma unroll
    for (int s=0;s<STAGES-1;s++){
        const float* ga = aptr + s*16;
        uint32_t da = aSt + s*(AST*4);
        cpa16(da, ga); cpa16(da+16, ga+4);
        const float* gb = bptr + (size_t)s*16*N;
        uint32_t db = bSt + s*(BST*4);
        cpa16(db, gb); cpa16(db+16, gb+4);
        asm volatile("cp.async.commit_group;" ::: "memory");
    }

    for (int c = 0; c < 64; c++){
        asm volatile("cp.async.wait_group 2;" ::: "memory");
        __syncthreads();
        if (c + STAGES-1 < 64){
            int cc = c + STAGES-1, st = cc & (STAGES-1);
            const float* ga = aptr + cc*16;
            uint32_t da = aSt + st*(AST*4);
            cpa16(da, ga); cpa16(da+16, ga+4);
            const float* gb = bptr + (size_t)cc*16*N;
            uint32_t db = bSt + st*(BST*4);
            cpa16(db, gb); cpa16(db+16, gb+4);
        }
        asm volatile("cp.async.commit_group;" ::: "memory");

        const float* Ad = Asm + (c & (STAGES-1))*AST;
        const float* Bd = Bsm + (c & (STAGES-1))*BST;
        #pragma unroll
        for (int kk=0;kk<2;kk++){
            uint32_t af[4][4];
            #pragma unroll
            for (int fm=0;fm<4;fm++){
                const float* ap = Ad + (wm*64 + fm*16)*APAD + kk*8;
                af[fm][0] = tf32u(ap[g*APAD + tig]);
                af[fm][1] = tf32u(ap[(g+8)*APAD + tig]);
                af[fm][2] = tf32u(ap[g*APAD + tig + 4]);
                af[fm][3] = tf32u(ap[(g+8)*APAD + tig + 4]);
            }
            uint32_t bf[4][2];
            #pragma unroll
            for (int fn=0;fn<4;fn++){
                const float* bp = Bd + (kk*8)*BPAD + wn*32 + fn*8 + g;
                bf[fn][0] = tf32u(bp[tig*BPAD]);
                bf[fn][1] = tf32u(bp[(tig+4)*BPAD]);
            }
            #pragma unroll
            for (int fm=0;fm<4;fm++)
                #pragma unroll
                for (int fn=0;fn<4;fn++)
                    mma_tf32_16n8k8(acc[fm][fn], af[fm], bf[fn]);
        }
    }

    // ---- epilogue ----
    #pragma unroll
    for (int fm=0;fm<4;fm++){
        int r0 = m0 + wm*64 + fm*16 + g;
        int r1 = r0 + 8;
        size_t ob0, ob1;
        if (MODE == 0){ ob0 = (size_t)r0*N; ob1 = (size_t)r1*N; }
        else {
            int bb0 = r0>>12, ss0 = r0&4095;
            int bb1 = r1>>12, ss1 = r1&4095;
            ob0 = (size_t)(ss0*BATCH+bb0)*DIMN;
            ob1 = (size_t)(ss1*BATCH+bb1)*DIMN;
        }
        #pragma unroll
        for (int fn=0;fn<4;fn++){
            int col = n0 + wn*32 + fn*8 + tig*2;
            float b0 = bias[col], b1 = bias[col+1];
            float2 v0 = make_float2(alpha*(acc[fm][fn][0]+b0),
                                    alpha*(acc[fm][fn][1]+b1));
            float2 v1 = make_float2(alpha*(acc[fm][fn][2]+b0),
                                    alpha*(acc[fm][fn][3]+b1));
            *(float2*)&Cout[ob0 + col] = v0;
            *(float2*)&Cout[ob1 + col] = v1;
        }
    }
}

// ---------------- row layernorm over DIM=1024, K and V in one launch ----------------
__global__ __launch_bounds__(256) void ln_rows_kv(
    float* __restrict__ Kx, float* __restrict__ Vx,
    const float* __restrict__ gamma, const float* __restrict__ beta)
{
    float* X = blockIdx.y ? Vx : Kx;
    int row = blockIdx.x;
    float* p = X + (size_t)row*DIMN;
    int tid = threadIdx.x;
    float4 v = *(float4*)(p + tid*4);
    float s  = v.x+v.y+v.z+v.w;
    float s2 = v.x*v.x+v.y*v.y+v.z*v.z+v.w*v.w;
    #pragma unroll
    for (int o=16;o>0;o>>=1){
        s  += __shfl_down_sync(0xffffffffu, s,  o);
        s2 += __shfl_down_sync(0xffffffffu, s2, o);
    }
    __shared__ float rs[8], rs2[8];
    int warp = tid>>5, lane = tid&31;
    if (lane==0){ rs[warp]=s; rs2[warp]=s2; }
    __syncthreads();
    if (tid==0){
        float S=0.f,S2=0.f;
        for(int i=0;i<8;i++){S+=rs[i];S2+=rs2[i];}
        float mean = S*(1.f/DIMN);
        float var  = S2*(1.f/DIMN) - mean*mean;
        rs[0]=mean; rs2[0]=rsqrtf(var + 1e-5f);
    }
    __syncthreads();
    float mean = rs[0], rstd = rs2[0];
    float4 g4 = *(const float4*)(gamma + tid*4);
    float4 b4 = *(const float4*)(beta  + tid*4);
    v.x = (v.x-mean)*rstd*g4.x + b4.x;
    v.y = (v.y-mean)*rstd*g4.y + b4.y;
    v.z = (v.z-mean)*rstd*g4.z + b4.z;
    v.w = (v.w-mean)*rstd*g4.w + b4.w;
    *(float4*)(p + tid*4) = v;
}

// ------- column softmax stats, split over sequence (partials) -------
__global__ __launch_bounds__(256) void colstats_part()
{
    int b  = blockIdx.x >> 4;
    int c0 = (blockIdx.x & 15) << 5;
    int sp = blockIdx.y;
    int cl = threadIdx.x & 31;
    int si = threadIdx.x >> 5;
    int c = c0 + cl;
    int sbeg = sp*(SEQ/NCS), send = sbeg + SEQ/NCS;
    float m = -1e30f, sum = 0.f;
    for (int s = sbeg + si; s < send; s += 8){
        float v = g_D[((size_t)(b*SEQ + s))*HL + c];
        if (v > m){ sum *= __expf(m - v); m = v; }
        sum += __expf(v - m);
    }
    __shared__ float sm[8][32], ss[8][32];
    sm[si][cl]=m; ss[si][cl]=sum;
    __syncthreads();
    if (si == 0){
        float M = sm[0][cl];
        #pragma unroll
        for (int k=1;k<8;k++) M = fmaxf(M, sm[k][cl]);
        float S = 0.f;
        #pragma unroll
        for (int k=0;k<8;k++) S += ss[k][cl]*__expf(sm[k][cl]-M);
        g_pm[sp][b*HL + c] = M;
        g_ps[sp][b*HL + c] = S;
    }
}

__global__ __launch_bounds__(256) void colstats_reduce()
{
    int i = blockIdx.x*256 + threadIdx.x;
    float M = g_pm[0][i];
    #pragma unroll
    for (int k=1;k<NCS;k++) M = fmaxf(M, g_pm[k][i]);
    float S = 0.f;
    #pragma unroll
    for (int k=0;k<NCS;k++) S += g_ps[k][i]*__expf(g_pm[k][i]-M);
    g_cmax[i] = M;
    g_cinv[i] = 1.f/S;
}

// ----- compressed landmarks, split over sequence (partials), 16-row tiles -----
__global__ __launch_bounds__(256) void compress_part()
{
    int b = blockIdx.x >> 4;
    int h = blockIdx.x & 15;
    int ch = blockIdx.y;                  // 0..NCH-1
    int tid = threadIdx.x;
    int d  = tid & 63;
    int lg = tid >> 6;
    __shared__ float wsh[16][32];
    __shared__ float ksh[16][64];
    __shared__ float vsh[16][64];
    __shared__ float msh[32], ish[32];
    if (tid < 32){
        msh[tid] = g_cmax[b*HL + h*32 + tid];
        ish[tid] = g_cinv[b*HL + h*32 + tid];
    }
    __syncthreads();
    float kacc[8], vacc[8];
    #pragma unroll
    for (int i=0;i<8;i++){ kacc[i]=0.f; vacc[i]=0.f; }

    int sbeg = ch*(SEQ/NCH), send = sbeg + SEQ/NCH;
    for (int s0=sbeg; s0<send; s0+=16){
        #pragma unroll
        for (int r=0;r<2;r++){
            int e = tid + r*256;
            int si = e >> 5, l = e & 31;
            float dv = g_D[((size_t)(b*SEQ + s0 + si))*HL + h*32 + l];
            wsh[si][l] = __expf(dv - msh[l]) * ish[l];
        }
        #pragma unroll
        for (int r=0;r<4;r++){
            int e = tid + r*256;
            int si = e >> 6, dd = e & 63;
            size_t off = ((size_t)(b*SEQ + s0 + si))*DIMN + h*64 + dd;
            ksh[si][dd] = g_K[off];
            vsh[si][dd] = g_V[off];
        }
        __syncthreads();
        #pragma unroll
        for (int si=0; si<16; si++){
            float kv = ksh[si][d], vv = vsh[si][d];
            #pragma unroll
            for (int i=0;i<8;i++){
                float w = wsh[si][lg*8+i];
                kacc[i] += w*kv; vacc[i] += w*vv;
            }
        }
        __syncthreads();
    }
    #pragma unroll
    for (int i=0;i<8;i++){
        int l = lg*8+i;
        size_t off = (((size_t)(b*NH+h))*LLC + l)*DHD + d;
        g_pKc[ch][off] = kacc[i];
        g_pVc[ch][off] = vacc[i];
    }
}

__global__ __launch_bounds__(256) void compress_reduce()
{
    int i = blockIdx.x*256 + threadIdx.x;
    float sk = 0.f, sv = 0.f;
    #pragma unroll
    for (int c=0;c<NCH;c++){ sk += g_pKc[c][i]; sv += g_pVc[c][i]; }
    g_Kc[i] = sk;
    g_Vc[i] = sv;
}

// ---- layernorm of Kc/Vc over (h,d) for each (b,l) ----
__global__ __launch_bounds__(256) void ln_small(
    float* __restrict__ X, const float* __restrict__ gamma,
    const float* __restrict__ beta)
{
    int b = blockIdx.x >> 5;
    int l = blockIdx.x & 31;
    int tid = threadIdx.x;
    float vals[4];
    float s=0.f, s2=0.f;
    #pragma unroll
    for (int k=0;k<4;k++){
        int e = tid + k*256;
        int h = e >> 6, dd = e & 63;
        float v = X[(((size_t)(b*NH+h))*LLC + l)*DHD + dd];
        vals[k]=v; s+=v; s2+=v*v;
    }
    #pragma unroll
    for (int o=16;o>0;o>>=1){
        s  += __shfl_down_sync(0xffffffffu, s,  o);
        s2 += __shfl_down_sync(0xffffffffu, s2, o);
    }
    __shared__ float rs[8], rs2[8];
    int warp = tid>>5, lane = tid&31;
    if (lane==0){ rs[warp]=s; rs2[warp]=s2; }
    __syncthreads();
    if (tid==0){
        float S=0.f,S2=0.f;
        for(int i=0;i<8;i++){S+=rs[i];S2+=rs2[i];}
        float mean = S*(1.f/DIMN);
        float var  = S2*(1.f/DIMN) - mean*mean;
        rs[0]=mean; rs2[0]=rsqrtf(var + 1e-5f);
    }
    __syncthreads();
    float mean = rs[0], rstd = rs2[0];
    #pragma unroll
    for (int k=0;k<4;k++){
        int e = tid + k*256;
        int h = e >> 6, dd = e & 63;
        X[(((size_t)(b*NH+h))*LLC + l)*DHD + dd] =
            (vals[k]-mean)*rstd*gamma[e] + beta[e];
    }
}

// ---------------- fused attention: 32 query rows per block ----------------
// smem: q[32][68], kc[32][68], vc[32][68], kw[40][68], vw[40][68], prob[32][48]
#define ATP 68
#define AT_Q   0
#define AT_KC  (32*ATP)
#define AT_VC  (64*ATP)
#define AT_KW  (96*ATP)
#define AT_VW  (136*ATP)
#define AT_PR  (176*ATP)
#define AT_SMEM ((176*ATP + 32*48)*4)   // 54016 bytes

__global__ __launch_bounds__(256) void attn32()
{
    extern __shared__ float s[];
    const int t = threadIdx.x;
    const int h = blockIdx.y, b = blockIdx.z;
    const int s0 = blockIdx.x*32;

    // ---- loads ----
    #pragma unroll
    for (int r=0;r<2;r++){
        int e = t + r*256;
        int row = e >> 4, c4 = (e & 15)*4;
        *(float4*)&s[AT_Q + row*ATP + c4] =
            *(const float4*)&g_Q[((size_t)(b*SEQ + s0 + row))*DIMN + h*64 + c4];
        size_t off = (((size_t)(b*NH+h))*LLC + row)*DHD + c4;
        *(float4*)&s[AT_KC + row*ATP + c4] = *(const float4*)&g_Kc[off];
        *(float4*)&s[AT_VC + row*ATP + c4] = *(const float4*)&g_Vc[off];
    }
    #pragma unroll
    for (int r=0;r<3;r++){
        int e = t + r*256;
        if (e < 640){
            int row = e >> 4, c4 = (e & 15)*4;
            int pos = s0 - EEXT + row;
            float4 kz = make_float4(0,0,0,0), vz = make_float4(0,0,0,0);
            if (pos >= 0 && pos < SEQ){
                size_t off = ((size_t)(b*SEQ+pos))*DIMN + h*64 + c4;
                kz = *(const float4*)&g_K[off];
                vz = *(const float4*)&g_V[off];
            }
            *(float4*)&s[AT_KW + row*ATP + c4] = kz;
            *(float4*)&s[AT_VW + row*ATP + c4] = vz;
        }
    }
    __syncthreads();

    // ---- logits: row w = t>>3, keys j = (t&7) + 8m ----
    const int w = t >> 3, j8 = t & 7;
    const int gl = w >> 3;
    const float* qr = &s[AT_Q + w*ATP];
    const float* krs[6];
    #pragma unroll
    for (int m=0;m<6;m++){
        int j = j8 + 8*m;
        krs[m] = (j < 32) ? &s[AT_KC + j*ATP]
                          : &s[AT_KW + (gl*8 + (j-32))*ATP];
    }
    float lg[6] = {0,0,0,0,0,0};
    #pragma unroll
    for (int c4=0;c4<16;c4++){
        float4 qv = *(const float4*)(qr + c4*4);
        #pragma unroll
        for (int m=0;m<6;m++){
            float4 kv = *(const float4*)(krs[m] + c4*4);
            lg[m] += qv.x*kv.x + qv.y*kv.y + qv.z*kv.z + qv.w*kv.w;
        }
    }
    #pragma unroll
    for (int m=4;m<6;m++){
        int jj = j8 + 8*m - 32;
        int pos = s0 + gl*8 - EEXT + jj;
        if (pos < 0 || pos >= SEQ) lg[m] = -1e30f;
    }
    // width-8 softmax
    float mx = lg[0];
    #pragma unroll
    for (int m=1;m<6;m++) mx = fmaxf(mx, lg[m]);
    #pragma unroll
    for (int o=4;o>0;o>>=1) mx = fmaxf(mx, __shfl_xor_sync(0xffffffffu, mx, o, 8));
    float sum = 0.f;
    #pragma unroll
    for (int m=0;m<6;m++){ lg[m] = __expf(lg[m]-mx); sum += lg[m]; }
    #pragma unroll
    for (int o=4;o>0;o>>=1) sum += __shfl_xor_sync(0xffffffffu, sum, o, 8);
    float inv = 1.f/sum;
    #pragma unroll
    for (int m=0;m<6;m++) s[AT_PR + w*48 + j8 + 8*m] = lg[m]*inv;
    __syncthreads();

    // ---- output: row w, dims d8..d8+7 ----
    const int d8 = (t & 7)*8;
    float4 oa = make_float4(0,0,0,0), ob = make_float4(0,0,0,0);
    const float* pr = &s[AT_PR + w*48];
    #pragma unroll
    for (int j=0;j<32;j++){
        float p = pr[j];
        const float* vr = &s[AT_VC + j*ATP + d8];
        float4 va = *(const float4*)vr, vb = *(const float4*)(vr+4);
        oa.x += p*va.x; oa.y += p*va.y; oa.z += p*va.z; oa.w += p*va.w;
        ob.x += p*vb.x; ob.y += p*vb.y; ob.z += p*vb.z; ob.w += p*vb.w;
    }
    #pragma unroll
    for (int j=0;j<16;j++){
        float p = pr[32+j];
        const float* vr = &s[AT_VW + (gl*8+j)*ATP + d8];
        float4 va = *(const float4*)vr, vb = *(const float4*)(vr+4);
        oa.x += p*va.x; oa.y += p*va.y; oa.z += p*va.z; oa.w += p*va.w;
        ob.x += p*vb.x; ob.y += p*vb.y; ob.z += p*vb.z; ob.w += p*vb.w;
    }
    size_t obase = ((size_t)(b*SEQ + s0 + w))*DIMN + h*64 + d8;
    *(float4*)&g_C[obase]   = oa;
    *(float4*)&g_C[obase+4] = ob;
}

// ---------------- launch ----------------
extern "C" void kernel_launch(void* const* d_in, const int* in_sizes, int n_in,
                              void* d_out, int out_size)
{
    const float* query = (const float*)d_in[0];
    const float* Wq = (const float*)d_in[1];
    const float* bq = (const float*)d_in[2];
    const float* Wk = (const float*)d_in[3];
    const float* bk = (const float*)d_in[4];
    const float* Wv = (const float*)d_in[5];
    const float* bv = (const float*)d_in[6];
    const float* Wo = (const float*)d_in[7];
    const float* bo = (const float*)d_in[8];
    const float* gl = (const float*)d_in[9];
    const float* bl = (const float*)d_in[10];
    const float* gs = (const float*)d_in[11];
    const float* bs = (const float*)d_in[12];
    const float* Wd = (const float*)d_in[13];
    const float* bd = (const float*)d_in[14];
    float* out = (float*)d_out;

    float *Qp, *Kp, *Vp, *Dp, *Cp, *Kcp, *Vcp;
    cudaGetSymbolAddress((void**)&Qp,  g_Q);
    cudaGetSymbolAddress((void**)&Kp,  g_K);
    cudaGetSymbolAddress((void**)&Vp,  g_V);
    cudaGetSymbolAddress((void**)&Dp,  g_D);
    cudaGetSymbolAddress((void**)&Cp,  g_C);
    cudaGetSymbolAddress((void**)&Kcp, g_Kc);
    cudaGetSymbolAddress((void**)&Vcp, g_Vc);

    static int cfg = 0;
    if (!cfg){
        cudaFuncSetAttribute(gemm_mma<0>, cudaFuncAttributeMaxDynamicSharedMemorySize, GM_SMEM);
        cudaFuncSetAttribute(gemm_mma<1>, cudaFuncAttributeMaxDynamicSharedMemorySize, GM_SMEM);
        cudaFuncSetAttribute(attn32,      cudaFuncAttributeMaxDynamicSharedMemorySize, AT_SMEM);
        cfg = 1;
    }

    // projections (tf32 HMMA, cp.async pipelined)
    gemm_mma<0><<<dim3(8,128), 256, GM_SMEM>>>(query, Wq, bq, Qp, DIMN, 0.125f);
    gemm_mma<0><<<dim3(8,128), 256, GM_SMEM>>>(query, Wk, bk, Kp, DIMN, 1.f);
    gemm_mma<0><<<dim3(8,128), 256, GM_SMEM>>>(query, Wv, bv, Vp, DIMN, 1.f);
    gemm_mma<0><<<dim3(4,128), 256, GM_SMEM>>>(query, Wd, bd, Dp, HL,   1.f);

    // K/V layernorm (g_l, b_l) — one launch for both tensors
    ln_rows_kv<<<dim3(MROWS,2), 256>>>(Kp, Vp, gl, bl);

    // head-score column softmax (split + reduce)
    colstats_part<<<dim3(64, NCS), 256>>>();
    colstats_reduce<<<8, 256>>>();

    // landmark compression (split + reduce)
    compress_part<<<dim3(64, NCH), 256>>>();
    compress_reduce<<<KCN/256, 256>>>();

    // landmark layernorm (g_s, b_s)
    ln_small<<<BATCH*LLC, 256>>>(Kcp, gs, bs);
    ln_small<<<BATCH*LLC, 256>>>(Vcp, gs, bs);

    // fused compressed + windowed attention (32 rows/block)
    attn32<<<dim3(NGRP/4, NH, BATCH), 256, AT_SMEM>>>();

    // output projection, scattered back to (SEQ, B, DIM)
    gemm_mma<1><<<dim3(8,128), 256, GM_SMEM>>>(Cp, Wo, bo, out, DIMN, 1.f);
}

// round 13
// speedup vs baseline: 2.8932x; 1.0604x over previous
#include <cuda_runtime.h>
#include <math.h>
#include <stdint.h>

#define SEQ   4096
#define BATCH 4
#define DIMN  1024
#define NH    16
#define DHD   64
#define LLC   32
#define WWIN  8
#define EEXT  4
#define NGRP  512
#define MROWS (SEQ*BATCH)   // 16384
#define HL    512           // H*L
#define NCAT  3584          // 3*1024 + 512 fused projection width
#define NCH   32            // compress seq-splits
#define NCS   8             // colstats seq-splits
#define KCN   (BATCH*NH*LLC*DHD)   // 131072

// ---------------- scratch (device globals: allocation-free) ----------------
__device__ float g_Q[(size_t)MROWS*DIMN];
__device__ float g_K[(size_t)MROWS*DIMN];
__device__ float g_V[(size_t)MROWS*DIMN];
__device__ float g_D[(size_t)MROWS*HL];
__device__ float g_cmax[BATCH*HL];
__device__ float g_cinv[BATCH*HL];
__device__ float g_Kc[KCN];
__device__ float g_Vc[KCN];
__device__ float g_C[(size_t)MROWS*DIMN];
__device__ float g_pKc[NCH][KCN];
__device__ float g_pVc[NCH][KCN];
__device__ float g_pm[NCS][BATCH*HL];
__device__ float g_ps[NCS][BATCH*HL];
// tf32-pre-rounded operands
__device__ float g_Xr[(size_t)MROWS*DIMN];
__device__ float g_Wcat[(size_t)DIMN*NCAT];
__device__ float g_Wor[(size_t)DIMN*DIMN];

__device__ __forceinline__ float to_tf32(float x){
    float r; asm("cvt.rna.tf32.f32 %0, %1;" : "=f"(r) : "f"(x)); return r;
}
__device__ __forceinline__ uint32_t smem_u32(const void* p){
    uint32_t a;
    asm("{ .reg .u64 t; cvta.to.shared.u64 t, %1; cvt.u32.u64 %0, t; }"
        : "=r"(a) : "l"(p));
    return a;
}
__device__ __forceinline__ void cpa16(uint32_t s, const float* g){
    asm volatile("cp.async.cg.shared.global [%0], [%1], 16;" :: "r"(s), "l"(g));
}
__device__ __forceinline__ void mma_tf32_16n8k8(
    float* c, const uint32_t* a, const uint32_t* b)
{
    asm volatile(
        "mma.sync.aligned.m16n8k8.row.col.f32.tf32.tf32.f32 "
        "{%0,%1,%2,%3}, {%4,%5,%6,%7}, {%8,%9}, {%0,%1,%2,%3};"
        : "+f"(c[0]), "+f"(c[1]), "+f"(c[2]), "+f"(c[3])
        : "r"(a[0]), "r"(a[1]), "r"(a[2]), "r"(a[3]),
          "r"(b[0]), "r"(b[1]));
}

// ---------------- elementwise tf32 rounding ----------------
__global__ __launch_bounds__(256) void round_tf32(
    const float* __restrict__ x, float* __restrict__ y, int n4)
{
    int i = blockIdx.x*256 + threadIdx.x;
    if (i < n4){
        float4 v = ((const float4*)x)[i];
        v.x = to_tf32(v.x); v.y = to_tf32(v.y);
        v.z = to_tf32(v.z); v.w = to_tf32(v.w);
        ((float4*)y)[i] = v;
    }
}

// ---- pack Wq|Wk|Wv|Wd (tf32-rounded) into g_Wcat[k][3584] ----
__global__ __launch_bounds__(256) void pack_w(
    const float* __restrict__ Wq, const float* __restrict__ Wk,
    const float* __restrict__ Wv, const float* __restrict__ Wd)
{
    int idx = blockIdx.x*256 + threadIdx.x;      // float4 index, 917504 total
    int row = idx / (NCAT/4);
    int col = (idx - row*(NCAT/4))*4;
    float4 v;
    if (col < 3072){
        int seg = col >> 10, sc = col & 1023;
        const float* src = (seg==0) ? Wq : (seg==1) ? Wk : Wv;
        v = *(const float4*)(src + (size_t)row*DIMN + sc);
    } else {
        v = *(const float4*)(Wd + (size_t)row*HL + (col - 3072));
    }
    v.x = to_tf32(v.x); v.y = to_tf32(v.y);
    v.z = to_tf32(v.z); v.w = to_tf32(v.w);
    *(float4*)&g_Wcat[(size_t)row*NCAT + col] = v;
}

// ---------------- shared GEMM compute core ----------------
#define STAGES 4
#define APAD 20
#define BPAD 136
#define AST (128*APAD)
#define BST (16*BPAD)
#define GM_SMEM (STAGES*(AST+BST)*4)   // 75776 bytes

// ---------------- fused Q/K/V/D projection GEMM ----------------
// A = g_Xr rows gathered from (S,B,DIM); B = g_Wcat [1024][3584].
// Output rows are PLAIN (b*SEQ+s) layout — what all downstream kernels read.
__global__ __launch_bounds__(256, 2) void gemm_qkvd(
    const float* __restrict__ bq, const float* __restrict__ bk,
    const float* __restrict__ bv, const float* __restrict__ bd)
{
    extern __shared__ float sh[];
    float* Asm = sh;
    float* Bsm = sh + STAGES*AST;

    const int tid  = threadIdx.x;
    const int lane = tid & 31, warp = tid >> 5;
    const int wm = warp & 1, wn = warp >> 1;
    const int g = lane >> 2, tig = lane & 3;
    const int m0 = blockIdx.y*128, n0 = blockIdx.x*128;

    const int seg = n0 >> 10;                       // 0..3
    float* Cout = (seg==0) ? g_Q : (seg==1) ? g_K : (seg==2) ? g_V : g_D;
    const float* bias = (seg==0) ? bq : (seg==1) ? bk : (seg==2) ? bv : bd;
    const int outN = (seg<3) ? DIMN : HL;
    const int colbase = (seg<3) ? (n0 & 1023) : (n0 - 3072);
    const float alpha = (seg==0) ? 0.125f : 1.f;

    const int ar = tid >> 1, ak = (tid & 1)*8;
    const float* aptr;
    {
        int gr = m0 + ar;                 // gr = b*SEQ + s
        int bb = gr >> 12, ss = gr & 4095;
        aptr = g_Xr + (size_t)(ss*BATCH + bb)*DIMN + ak;   // input is (S,B,DIM)
    }
    const int br = tid >> 4, bn = (tid & 15)*8;
    const float* bptr = g_Wcat + (size_t)br*NCAT + n0 + bn;

    const uint32_t aSt = smem_u32(Asm) + (uint32_t)(ar*APAD + ak)*4u;
    const uint32_t bSt = smem_u32(Bsm) + (uint32_t)(br*BPAD + bn)*4u;

    float acc[4][4][4];
    #pragma unroll
    for (int i=0;i<4;i++)
        #pragma unroll
        for (int j=0;j<4;j++)
            #pragma unroll
            for (int k=0;k<4;k++) acc[i][j][k]=0.f;

    #pragma unroll
    for (int s=0;s<STAGES-1;s++){
        const float* ga = aptr + s*16;
        uint32_t da = aSt + s*(AST*4);
        cpa16(da, ga); cpa16(da+16, ga+4);
        const float* gb = bptr + (size_t)s*16*NCAT;
        uint32_t db = bSt + s*(BST*4);
        cpa16(db, gb); cpa16(db+16, gb+4);
        asm volatile("cp.async.commit_group;" ::: "memory");
    }

    for (int c = 0; c < 64; c++){
        asm volatile("cp.async.wait_group 2;" ::: "memory");
        __syncthreads();
        if (c + STAGES-1 < 64){
            int cc = c + STAGES-1, st = cc & (STAGES-1);
            const float* ga = aptr + cc*16;
            uint32_t da = aSt + st*(AST*4);
            cpa16(da, ga); cpa16(da+16, ga+4);
            const float* gb = bptr + (size_t)cc*16*NCAT;
            uint32_t db = bSt + st*(BST*4);
            cpa16(db, gb); cpa16(db+16, gb+4);
        }
        asm volatile("cp.async.commit_group;" ::: "memory");

        const uint32_t* Ad = (const uint32_t*)(Asm + (c & (STAGES-1))*AST);
        const uint32_t* Bd = (const uint32_t*)(Bsm + (c & (STAGES-1))*BST);
        #pragma unroll
        for (int kk=0;kk<2;kk++){
            uint32_t af[4][4];
            #pragma unroll
            for (int fm=0;fm<4;fm++){
                const uint32_t* ap = Ad + (wm*64 + fm*16)*APAD + kk*8;
                af[fm][0] = ap[g*APAD + tig];
                af[fm][1] = ap[(g+8)*APAD + tig];
                af[fm][2] = ap[g*APAD + tig + 4];
                af[fm][3] = ap[(g+8)*APAD + tig + 4];
            }
            uint32_t bf[4][2];
            #pragma unroll
            for (int fn=0;fn<4;fn++){
                const uint32_t* bp = Bd + (kk*8)*BPAD + wn*32 + fn*8 + g;
                bf[fn][0] = bp[tig*BPAD];
                bf[fn][1] = bp[(tig+4)*BPAD];
            }
            #pragma unroll
            for (int fm=0;fm<4;fm++)
                #pragma unroll
                for (int fn=0;fn<4;fn++)
                    mma_tf32_16n8k8(acc[fm][fn], af[fm], bf[fn]);
        }
    }

    // ---- epilogue: PLAIN row-major store (row = b*SEQ+s) ----
    #pragma unroll
    for (int fm=0;fm<4;fm++){
        int r0 = m0 + wm*64 + fm*16 + g;
        int r1 = r0 + 8;
        size_t ob0 = (size_t)r0*outN;
        size_t ob1 = (size_t)r1*outN;
        #pragma unroll
        for (int fn=0;fn<4;fn++){
            int col = colbase + wn*32 + fn*8 + tig*2;
            float b0 = bias[col], b1 = bias[col+1];
            float2 v0 = make_float2(alpha*(acc[fm][fn][0]+b0),
                                    alpha*(acc[fm][fn][1]+b1));
            float2 v1 = make_float2(alpha*(acc[fm][fn][2]+b0),
                                    alpha*(acc[fm][fn][3]+b1));
            *(float2*)&Cout[ob0 + col] = v0;
            *(float2*)&Cout[ob1 + col] = v1;
        }
    }
}

// ---------------- output projection GEMM (pre-rounded operands) ----------------
// A = g_C plain (b*SEQ+s) rows; C scattered back to (S,B,DIM).
__global__ __launch_bounds__(256, 2) void gemm_out(
    const float* __restrict__ A, const float* __restrict__ W,
    const float* __restrict__ bias, float* __restrict__ Cout)
{
    extern __shared__ float sh[];
    float* Asm = sh;
    float* Bsm = sh + STAGES*AST;

    const int tid  = threadIdx.x;
    const int lane = tid & 31, warp = tid >> 5;
    const int wm = warp & 1, wn = warp >> 1;
    const int g = lane >> 2, tig = lane & 3;
    const int m0 = blockIdx.y*128, n0 = blockIdx.x*128;

    const int ar = tid >> 1, ak = (tid & 1)*8;
    const float* aptr = A + (size_t)(m0 + ar)*DIMN + ak;
    const int br = tid >> 4, bn = (tid & 15)*8;
    const float* bptr = W + (size_t)br*DIMN + n0 + bn;

    const uint32_t aSt = smem_u32(Asm) + (uint32_t)(ar*APAD + ak)*4u;
    const uint32_t bSt = smem_u32(Bsm) + (uint32_t)(br*BPAD + bn)*4u;

    float acc[4][4][4];
    #pragma unroll
    for (int i=0;i<4;i++)
        #pragma unroll
        for (int j=0;j<4;j++)
            #pragma unroll
            for (int k=0;k<4;k++) acc[i][j][k]=0.f;

    #pragma unroll
    for (int s=0;s<STAGES-1;s++){
        const float* ga = aptr + s*16;
        uint32_t da = aSt + s*(AST*4);
        cpa16(da, ga); cpa16(da+16, ga+4);
        const float* gb = bptr + (size_t)s*16*DIMN;
        uint32_t db = bSt + s*(BST*4);
        cpa16(db, gb); cpa16(db+16, gb+4);
        asm volatile("cp.async.commit_group;" ::: "memory");
    }

    for (int c = 0; c < 64; c++){
        asm volatile("cp.async.wait_group 2;" ::: "memory");
        __syncthreads();
        if (c + STAGES-1 < 64){
            int cc = c + STAGES-1, st = cc & (STAGES-1);
            const float* ga = aptr + cc*16;
            uint32_t da = aSt + st*(AST*4);
            cpa16(da, ga); cpa16(da+16, ga+4);
            const float* gb = bptr + (size_t)cc*16*DIMN;
            uint32_t db = bSt + st*(BST*4);
            cpa16(db, gb); cpa16(db+16, gb+4);
        }
        asm volatile("cp.async.commit_group;" ::: "memory");

        const uint32_t* Ad = (const uint32_t*)(Asm + (c & (STAGES-1))*AST);
        const uint32_t* Bd = (const uint32_t*)(Bsm + (c & (STAGES-1))*BST);
        #pragma unroll
        for (int kk=0;kk<2;kk++){
            uint32_t af[4][4];
            #pragma unroll
            for (int fm=0;fm<4;fm++){
                const uint32_t* ap = Ad + (wm*64 + fm*16)*APAD + kk*8;
                af[fm][0] = ap[g*APAD + tig];
                af[fm][1] = ap[(g+8)*APAD + tig];
                af[fm][2] = ap[g*APAD + tig + 4];
                af[fm][3] = ap[(g+8)*APAD + tig + 4];
            }
            uint32_t bf[4][2];
            #pragma unroll
            for (int fn=0;fn<4;fn++){
                const uint32_t* bp = Bd + (kk*8)*BPAD + wn*32 + fn*8 + g;
                bf[fn][0] = bp[tig*BPAD];
                bf[fn][1] = bp[(tig+4)*BPAD];
            }
            #pragma unroll
            for (int fm=0;fm<4;fm++)
                #pragma unroll
                for (int fn=0;fn<4;fn++)
                    mma_tf32_16n8k8(acc[fm][fn], af[fm], bf[fn]);
        }
    }

    #pragma unroll
    for (int fm=0;fm<4;fm++){
        int r0 = m0 + wm*64 + fm*16 + g;
        int r1 = r0 + 8;
        int bb0 = r0>>12, ss0 = r0&4095;
        int bb1 = r1>>12, ss1 = r1&4095;
        size_t ob0 = (size_t)(ss0*BATCH+bb0)*DIMN;
        size_t ob1 = (size_t)(ss1*BATCH+bb1)*DIMN;
        #pragma unroll
        for (int fn=0;fn<4;fn++){
            int col = n0 + wn*32 + fn*8 + tig*2;
            float b0 = bias[col], b1 = bias[col+1];
            float2 v0 = make_float2(acc[fm][fn][0]+b0, acc[fm][fn][1]+b1);
            float2 v1 = make_float2(acc[fm][fn][2]+b0, acc[fm][fn][3]+b1);
            *(float2*)&Cout[ob0 + col] = v0;
            *(float2*)&Cout[ob1 + col] = v1;
        }
    }
}

// ---------------- row layernorm over DIM=1024, K and V in one launch ----------------
__global__ __launch_bounds__(256) void ln_rows_kv(
    const float* __restrict__ gamma, const float* __restrict__ beta)
{
    float* X = blockIdx.y ? g_V : g_K;
    int row = blockIdx.x;
    float* p = X + (size_t)row*DIMN;
    int tid = threadIdx.x;
    float4 v = *(float4*)(p + tid*4);
    float s  = v.x+v.y+v.z+v.w;
    float s2 = v.x*v.x+v.y*v.y+v.z*v.z+v.w*v.w;
    #pragma unroll
    for (int o=16;o>0;o>>=1){
        s  += __shfl_down_sync(0xffffffffu, s,  o);
        s2 += __shfl_down_sync(0xffffffffu, s2, o);
    }
    __shared__ float rs[8], rs2[8];
    int warp = tid>>5, lane = tid&31;
    if (lane==0){ rs[warp]=s; rs2[warp]=s2; }
    __syncthreads();
    if (tid==0){
        float S=0.f,S2=0.f;
        for(int i=0;i<8;i++){S+=rs[i];S2+=rs2[i];}
        float mean = S*(1.f/DIMN);
        float var  = S2*(1.f/DIMN) - mean*mean;
        rs[0]=mean; rs2[0]=rsqrtf(var + 1e-5f);
    }
    __syncthreads();
    float mean = rs[0], rstd = rs2[0];
    float4 g4 = *(const float4*)(gamma + tid*4);
    float4 b4 = *(const float4*)(beta  + tid*4);
    v.x = (v.x-mean)*rstd*g4.x + b4.x;
    v.y = (v.y-mean)*rstd*g4.y + b4.y;
    v.z = (v.z-mean)*rstd*g4.z + b4.z;
    v.w = (v.w-mean)*rstd*g4.w + b4.w;
    *(float4*)(p + tid*4) = v;
}

// ------- column softmax stats, split over sequence (partials) -------
__global__ __launch_bounds__(256) void colstats_part()
{
    int b  = blockIdx.x >> 4;
    int c0 = (blockIdx.x & 15) << 5;
    int sp = blockIdx.y;
    int cl = threadIdx.x & 31;
    int si = threadIdx.x >> 5;
    int c = c0 + cl;
    int sbeg = sp*(SEQ/NCS), send = sbeg + SEQ/NCS;
    float m = -1e30f, sum = 0.f;
    for (int s = sbeg + si; s < send; s += 8){
        float v = g_D[((size_t)(b*SEQ + s))*HL + c];
        if (v > m){ sum *= __expf(m - v); m = v; }
        sum += __expf(v - m);
    }
    __shared__ float sm[8][32], ss[8][32];
    sm[si][cl]=m; ss[si][cl]=sum;
    __syncthreads();
    if (si == 0){
        float M = sm[0][cl];
        #pragma unroll
        for (int k=1;k<8;k++) M = fmaxf(M, sm[k][cl]);
        float S = 0.f;
        #pragma unroll
        for (int k=0;k<8;k++) S += ss[k][cl]*__expf(sm[k][cl]-M);
        g_pm[sp][b*HL + c] = M;
        g_ps[sp][b*HL + c] = S;
    }
}

__global__ __launch_bounds__(256) void colstats_reduce()
{
    int i = blockIdx.x*256 + threadIdx.x;
    float M = g_pm[0][i];
    #pragma unroll
    for (int k=1;k<NCS;k++) M = fmaxf(M, g_pm[k][i]);
    float S = 0.f;
    #pragma unroll
    for (int k=0;k<NCS;k++) S += g_ps[k][i]*__expf(g_pm[k][i]-M);
    g_cmax[i] = M;
    g_cinv[i] = 1.f/S;
}

// ----- compressed landmarks, split over sequence (partials), 16-row tiles -----
__global__ __launch_bounds__(256) void compress_part()
{
    int b = blockIdx.x >> 4;
    int h = blockIdx.x & 15;
    int ch = blockIdx.y;
    int tid = threadIdx.x;
    int d  = tid & 63;
    int lg = tid >> 6;
    __shared__ float wsh[16][32];
    __shared__ float ksh[16][64];
    __shared__ float vsh[16][64];
    __shared__ float msh[32], ish[32];
    if (tid < 32){
        msh[tid] = g_cmax[b*HL + h*32 + tid];
        ish[tid] = g_cinv[b*HL + h*32 + tid];
    }
    __syncthreads();
    float kacc[8], vacc[8];
    #pragma unroll
    for (int i=0;i<8;i++){ kacc[i]=0.f; vacc[i]=0.f; }

    int sbeg = ch*(SEQ/NCH), send = sbeg + SEQ/NCH;
    for (int s0=sbeg; s0<send; s0+=16){
        #pragma unroll
        for (int r=0;r<2;r++){
            int e = tid + r*256;
            int si = e >> 5, l = e & 31;
            float dv = g_D[((size_t)(b*SEQ + s0 + si))*HL + h*32 + l];
            wsh[si][l] = __expf(dv - msh[l]) * ish[l];
        }
        #pragma unroll
        for (int r=0;r<4;r++){
            int e = tid + r*256;
            int si = e >> 6, dd = e & 63;
            size_t off = ((size_t)(b*SEQ + s0 + si))*DIMN + h*64 + dd;
            ksh[si][dd] = g_K[off];
            vsh[si][dd] = g_V[off];
        }
        __syncthreads();
        #pragma unroll
        for (int si=0; si<16; si++){
            float kv = ksh[si][d], vv = vsh[si][d];
            #pragma unroll
            for (int i=0;i<8;i++){
                float w = wsh[si][lg*8+i];
                kacc[i] += w*kv; vacc[i] += w*vv;
            }
        }
        __syncthreads();
    }
    #pragma unroll
    for (int i=0;i<8;i++){
        int l = lg*8+i;
        size_t off = (((size_t)(b*NH+h))*LLC + l)*DHD + d;
        g_pKc[ch][off] = kacc[i];
        g_pVc[ch][off] = vacc[i];
    }
}

__global__ __launch_bounds__(256) void compress_reduce()
{
    int i = blockIdx.x*256 + threadIdx.x;
    float sk = 0.f, sv = 0.f;
    #pragma unroll
    for (int c=0;c<NCH;c++){ sk += g_pKc[c][i]; sv += g_pVc[c][i]; }
    g_Kc[i] = sk;
    g_Vc[i] = sv;
}

// ---- layernorm of Kc/Vc over (h,d) for each (b,l), both in one launch ----
__global__ __launch_bounds__(256) void ln_small2(
    const float* __restrict__ gamma, const float* __restrict__ beta)
{
    float* X = blockIdx.y ? g_Vc : g_Kc;
    int b = blockIdx.x >> 5;
    int l = blockIdx.x & 31;
    int tid = threadIdx.x;
    float vals[4];
    float s=0.f, s2=0.f;
    #pragma unroll
    for (int k=0;k<4;k++){
        int e = tid + k*256;
        int h = e >> 6, dd = e & 63;
        float v = X[(((size_t)(b*NH+h))*LLC + l)*DHD + dd];
        vals[k]=v; s+=v; s2+=v*v;
    }
    #pragma unroll
    for (int o=16;o>0;o>>=1){
        s  += __shfl_down_sync(0xffffffffu, s,  o);
        s2 += __shfl_down_sync(0xffffffffu, s2, o);
    }
    __shared__ float rs[8], rs2[8];
    int warp = tid>>5, lane = tid&31;
    if (lane==0){ rs[warp]=s; rs2[warp]=s2; }
    __syncthreads();
    if (tid==0){
        float S=0.f,S2=0.f;
        for(int i=0;i<8;i++){S+=rs[i];S2+=rs2[i];}
        float mean = S*(1.f/DIMN);
        float var  = S2*(1.f/DIMN) - mean*mean;
        rs[0]=mean; rs2[0]=rsqrtf(var + 1e-5f);
    }
    __syncthreads();
    float mean = rs[0], rstd = rs2[0];
    #pragma unroll
    for (int k=0;k<4;k++){
        int e = tid + k*256;
        int h = e >> 6, dd = e & 63;
        X[(((size_t)(b*NH+h))*LLC + l)*DHD + dd] =
            (vals[k]-mean)*rstd*gamma[e] + beta[e];
    }
}

// ---------------- fused attention: 32 query rows per block ----------------
#define ATP 68
#define AT_Q   0
#define AT_KC  (32*ATP)
#define AT_VC  (64*ATP)
#define AT_KW  (96*ATP)
#define AT_VW  (136*ATP)
#define AT_PR  (176*ATP)
#define AT_SMEM ((176*ATP + 32*48)*4)   // 54016 bytes

__global__ __launch_bounds__(256) void attn32()
{
    extern __shared__ float s[];
    const int t = threadIdx.x;
    const int h = blockIdx.y, b = blockIdx.z;
    const int s0 = blockIdx.x*32;

    #pragma unroll
    for (int r=0;r<2;r++){
        int e = t + r*256;
        int row = e >> 4, c4 = (e & 15)*4;
        *(float4*)&s[AT_Q + row*ATP + c4] =
            *(const float4*)&g_Q[((size_t)(b*SEQ + s0 + row))*DIMN + h*64 + c4];
        size_t off = (((size_t)(b*NH+h))*LLC + row)*DHD + c4;
        *(float4*)&s[AT_KC + row*ATP + c4] = *(const float4*)&g_Kc[off];
        *(float4*)&s[AT_VC + row*ATP + c4] = *(const float4*)&g_Vc[off];
    }
    #pragma unroll
    for (int r=0;r<3;r++){
        int e = t + r*256;
        if (e < 640){
            int row = e >> 4, c4 = (e & 15)*4;
            int pos = s0 - EEXT + row;
            float4 kz = make_float4(0,0,0,0), vz = make_float4(0,0,0,0);
            if (pos >= 0 && pos < SEQ){
                size_t off = ((size_t)(b*SEQ+pos))*DIMN + h*64 + c4;
                kz = *(const float4*)&g_K[off];
                vz = *(const float4*)&g_V[off];
            }
            *(float4*)&s[AT_KW + row*ATP + c4] = kz;
            *(float4*)&s[AT_VW + row*ATP + c4] = vz;
        }
    }
    __syncthreads();

    const int w = t >> 3, j8 = t & 7;
    const int gl = w >> 3;
    const float* qr = &s[AT_Q + w*ATP];
    const float* krs[6];
    #pragma unroll
    for (int m=0;m<6;m++){
        int j = j8 + 8*m;
        krs[m] = (j < 32) ? &s[AT_KC + j*ATP]
                          : &s[AT_KW + (gl*8 + (j-32))*ATP];
    }
    float lg[6] = {0,0,0,0,0,0};
    #pragma unroll
    for (int c4=0;c4<16;c4++){
        float4 qv = *(const float4*)(qr + c4*4);
        #pragma unroll
        for (int m=0;m<6;m++){
            float4 kv = *(const float4*)(krs[m] + c4*4);
            lg[m] += qv.x*kv.x + qv.y*kv.y + qv.z*kv.z + qv.w*kv.w;
        }
    }
    #pragma unroll
    for (int m=4;m<6;m++){
        int jj = j8 + 8*m - 32;
        int pos = s0 + gl*8 - EEXT + jj;
        if (pos < 0 || pos >= SEQ) lg[m] = -1e30f;
    }
    float mx = lg[0];
    #pragma unroll
    for (int m=1;m<6;m++) mx = fmaxf(mx, lg[m]);
    #pragma unroll
    for (int o=4;o>0;o>>=1) mx = fmaxf(mx, __shfl_xor_sync(0xffffffffu, mx, o, 8));
    float sum = 0.f;
    #pragma unroll
    for (int m=0;m<6;m++){ lg[m] = __expf(lg[m]-mx); sum += lg[m]; }
    #pragma unroll
    for (int o=4;o>0;o>>=1) sum += __shfl_xor_sync(0xffffffffu, sum, o, 8);
    float inv = 1.f/sum;
    #pragma unroll
    for (int m=0;m<6;m++) s[AT_PR + w*48 + j8 + 8*m] = lg[m]*inv;
    __syncthreads();

    const int d8 = (t & 7)*8;
    float4 oa = make_float4(0,0,0,0), ob = make_float4(0,0,0,0);
    const float* pr = &s[AT_PR + w*48];
    #pragma unroll
    for (int j=0;j<32;j++){
        float p = pr[j];
        const float* vr = &s[AT_VC + j*ATP + d8];
        float4 va = *(const float4*)vr, vb = *(const float4*)(vr+4);
        oa.x += p*va.x; oa.y += p*va.y; oa.z += p*va.z; oa.w += p*va.w;
        ob.x += p*vb.x; ob.y += p*vb.y; ob.z += p*vb.z; ob.w += p*vb.w;
    }
    #pragma unroll
    for (int j=0;j<16;j++){
        float p = pr[32+j];
        const float* vr = &s[AT_VW + (gl*8+j)*ATP + d8];
        float4 va = *(const float4*)vr, vb = *(const float4*)(vr+4);
        oa.x += p*va.x; oa.y += p*va.y; oa.z += p*va.z; oa.w += p*va.w;
        ob.x += p*vb.x; ob.y += p*vb.y; ob.z += p*vb.z; ob.w += p*vb.w;
    }
    // store tf32-rounded: g_C feeds the tf32 output GEMM
    oa.x=to_tf32(oa.x); oa.y=to_tf32(oa.y); oa.z=to_tf32(oa.z); oa.w=to_tf32(oa.w);
    ob.x=to_tf32(ob.x); ob.y=to_tf32(ob.y); ob.z=to_tf32(ob.z); ob.w=to_tf32(ob.w);
    size_t obase = ((size_t)(b*SEQ + s0 + w))*DIMN + h*64 + d8;
    *(float4*)&g_C[obase]   = oa;
    *(float4*)&g_C[obase+4] = ob;
}

// ---------------- launch ----------------
extern "C" void kernel_launch(void* const* d_in, const int* in_sizes, int n_in,
                              void* d_out, int out_size)
{
    const float* query = (const float*)d_in[0];
    const float* Wq = (const float*)d_in[1];
    const float* bq = (const float*)d_in[2];
    const float* Wk = (const float*)d_in[3];
    const float* bk = (const float*)d_in[4];
    const float* Wv = (const float*)d_in[5];
    const float* bv = (const float*)d_in[6];
    const float* Wo = (const float*)d_in[7];
    const float* bo = (const float*)d_in[8];
    const float* gl = (const float*)d_in[9];
    const float* bl = (const float*)d_in[10];
    const float* gs = (const float*)d_in[11];
    const float* bs = (const float*)d_in[12];
    const float* Wd = (const float*)d_in[13];
    const float* bd = (const float*)d_in[14];
    float* out = (float*)d_out;

    float *Cp, *Xr, *Wor;
    cudaGetSymbolAddress((void**)&Cp,  g_C);
    cudaGetSymbolAddress((void**)&Xr,  g_Xr);
    cudaGetSymbolAddress((void**)&Wor, g_Wor);

    static int cfg = 0;
    if (!cfg){
        cudaFuncSetAttribute(gemm_qkvd, cudaFuncAttributeMaxDynamicSharedMemorySize, GM_SMEM);
        cudaFuncSetAttribute(gemm_out,  cudaFuncAttributeMaxDynamicSharedMemorySize, GM_SMEM);
        cudaFuncSetAttribute(attn32,    cudaFuncAttributeMaxDynamicSharedMemorySize, AT_SMEM);
        cfg = 1;
    }

    const int X4  = MROWS*DIMN/4;      // 16384 blocks
    const int W44 = DIMN*DIMN/4;       // 1024 blocks
    const int WC4 = DIMN*NCAT/4;       // 3584 blocks

    // pre-round operands (X, fused Wq|Wk|Wv|Wd, Wo)
    round_tf32<<<X4/256, 256>>>(query, Xr, X4);
    pack_w<<<WC4/256, 256>>>(Wq, Wk, Wv, Wd);
    round_tf32<<<W44/256, 256>>>(Wo, Wor, W44);

    // fused Q/K/V/D projection (one launch, 3584 CTAs)
    gemm_qkvd<<<dim3(28,128), 256, GM_SMEM>>>(bq, bk, bv, bd);

    // K/V layernorm (g_l, b_l)
    ln_rows_kv<<<dim3(MROWS,2), 256>>>(gl, bl);

    // head-score column softmax (split + reduce)
    colstats_part<<<dim3(64, NCS), 256>>>();
    colstats_reduce<<<8, 256>>>();

    // landmark compression (split + reduce)
    compress_part<<<dim3(64, NCH), 256>>>();
    compress_reduce<<<KCN/256, 256>>>();

    // landmark layernorm (g_s, b_s), Kc and Vc in one launch
    ln_small2<<<dim3(BATCH*LLC, 2), 256>>>(gs, bs);

    // fused compressed + windowed attention (32 rows/block)
    attn32<<<dim3(NGRP/4, NH, BATCH), 256, AT_SMEM>>>();

    // output projection, scattered back to (SEQ, B, DIM)
    gemm_out<<<dim3(8,128), 256, GM_SMEM>>>(Cp, Wor, bo, out);
}

// round 14
// speedup vs baseline: 4.9741x; 1.7192x over previous
#include <cuda_runtime.h>
#include <cuda_fp16.h>
#include <math.h>
#include <stdint.h>

#define SEQ   4096
#define BATCH 4
#define DIMN  1024
#define NH    16
#define DHD   64
#define LLC   32
#define WWIN  8
#define EEXT  4
#define NGRP  512
#define MROWS (SEQ*BATCH)   // 16384
#define HL    512           // H*L
#define NCAT  3584          // 3*1024 + 512 fused projection width
#define NCH   32            // compress seq-splits
#define NCS   8             // colstats seq-splits
#define KCN   (BATCH*NH*LLC*DHD)   // 131072

// ---------------- scratch (device globals: allocation-free) ----------------
__device__ float g_Q[(size_t)MROWS*DIMN];
__device__ float g_K[(size_t)MROWS*DIMN];
__device__ float g_V[(size_t)MROWS*DIMN];
__device__ float g_D[(size_t)MROWS*HL];
__device__ float g_cmax[BATCH*HL];
__device__ float g_cinv[BATCH*HL];
__device__ float g_Kc[KCN];
__device__ float g_Vc[KCN];
__device__ float g_pKc[NCH][KCN];
__device__ float g_pVc[NCH][KCN];
__device__ float g_pm[NCS][BATCH*HL];
__device__ float g_ps[NCS][BATCH*HL];
// fp16 GEMM operands
__device__ __half g_Xh[(size_t)MROWS*DIMN];     // (S,B,DIM) layout, halved
__device__ __half g_WcatH[(size_t)NCAT*DIMN];   // [n][k] transposed fused weights
__device__ __half g_WoTh[(size_t)DIMN*DIMN];    // [n][k] transposed Wo
__device__ __half g_Ch[(size_t)MROWS*DIMN];     // attention output (plain rows)

__device__ __forceinline__ uint32_t smem_u32(const void* p){
    uint32_t a;
    asm("{ .reg .u64 t; cvta.to.shared.u64 t, %1; cvt.u32.u64 %0, t; }"
        : "=r"(a) : "l"(p));
    return a;
}
__device__ __forceinline__ void cpa16(uint32_t s, const void* g){
    asm volatile("cp.async.cg.shared.global [%0], [%1], 16;" :: "r"(s), "l"(g));
}
__device__ __forceinline__ void ldsm4(uint32_t* r, uint32_t addr){
    asm volatile("ldmatrix.sync.aligned.m8n8.x4.shared.b16 {%0,%1,%2,%3}, [%4];"
        : "=r"(r[0]), "=r"(r[1]), "=r"(r[2]), "=r"(r[3]) : "r"(addr));
}
__device__ __forceinline__ void mma_f16(float* c, const uint32_t* a, const uint32_t* b){
    asm volatile(
        "mma.sync.aligned.m16n8k16.row.col.f32.f16.f16.f32 "
        "{%0,%1,%2,%3}, {%4,%5,%6,%7}, {%8,%9}, {%0,%1,%2,%3};"
        : "+f"(c[0]), "+f"(c[1]), "+f"(c[2]), "+f"(c[3])
        : "r"(a[0]), "r"(a[1]), "r"(a[2]), "r"(a[3]),
          "r"(b[0]), "r"(b[1]));
}

// ---------------- elementwise f32 -> f16 ----------------
__global__ __launch_bounds__(256) void round_half(
    const float* __restrict__ x, __half* __restrict__ y, int n4)
{
    int i = blockIdx.x*256 + threadIdx.x;
    if (i < n4){
        float4 v = ((const float4*)x)[i];
        __half2 h0 = __floats2half2_rn(v.x, v.y);
        __half2 h1 = __floats2half2_rn(v.z, v.w);
        uint2 pk = make_uint2(*(uint32_t*)&h0, *(uint32_t*)&h1);
        ((uint2*)y)[i] = pk;
    }
}

// ---- transpose+round fused weights: g_WcatH[n][k] = h(W*[k][n]) ----
__global__ __launch_bounds__(256) void pack_wT(
    const float* __restrict__ Wq, const float* __restrict__ Wk,
    const float* __restrict__ Wv, const float* __restrict__ Wd)
{
    __shared__ float t[32][33];
    int n0 = blockIdx.x*32, k0 = blockIdx.y*32;
    int x = threadIdx.x, y = threadIdx.y;
    #pragma unroll
    for (int i=0;i<32;i+=8){
        int k = k0 + y + i, n = n0 + x;
        float v;
        if (n < 3072){
            int seg = n >> 10;
            const float* src = (seg==0) ? Wq : (seg==1) ? Wk : Wv;
            v = src[(size_t)k*DIMN + (n & 1023)];
        } else {
            v = Wd[(size_t)k*HL + (n - 3072)];
        }
        t[y+i][x] = v;
    }
    __syncthreads();
    #pragma unroll
    for (int i=0;i<32;i+=8)
        g_WcatH[(size_t)(n0+y+i)*DIMN + k0+x] = __float2half(t[x][y+i]);
}

// ---- transpose+round Wo: g_WoTh[n][k] = h(Wo[k][n]) ----
__global__ __launch_bounds__(256) void pack_woT(const float* __restrict__ Wo)
{
    __shared__ float t[32][33];
    int n0 = blockIdx.x*32, k0 = blockIdx.y*32;
    int x = threadIdx.x, y = threadIdx.y;
    #pragma unroll
    for (int i=0;i<32;i+=8)
        t[y+i][x] = Wo[(size_t)(k0+y+i)*DIMN + n0+x];
    __syncthreads();
    #pragma unroll
    for (int i=0;i<32;i+=8)
        g_WoTh[(size_t)(n0+y+i)*DIMN + k0+x] = __float2half(t[x][y+i]);
}

// ---------------- fp16 HMMA GEMM core ----------------
// CTA tile 128x128, 8 warps (2m x 4n), warp tile 64x32, K-chunk 32 halfs,
// 4-stage cp.async. A smem [128][40] halfs, B smem [128][40] halfs ([n][k]).
#define STAGES 4
#define HROW 40
#define HSTB (128*HROW*2)          // bytes per stage (10240)
#define GH_SMEM (STAGES*2*HSTB)    // 81920 bytes

// MODE 0: A rows gathered from (S,B,DIM) g_Xh, 4-way segmented output (QKVD).
// MODE 1: A = g_Ch plain rows, single output scattered to (S,B,DIM).
template<int MODE>
__global__ __launch_bounds__(256, 2) void gemm_h(
    const __half* __restrict__ Ah, const __half* __restrict__ Bh,
    const float* __restrict__ bq, const float* __restrict__ bk,
    const float* __restrict__ bv, const float* __restrict__ bd,
    float* __restrict__ OutM1)
{
    extern __shared__ char sh[];
    const uint32_t sbase = smem_u32(sh);
    const uint32_t bbase = sbase + STAGES*HSTB;

    const int tid  = threadIdx.x;
    const int lane = tid & 31, warp = tid >> 5;
    const int wm = warp & 1, wn = warp >> 1;
    const int g = lane >> 2, tig = lane & 3;
    const int m0 = blockIdx.y*128, n0 = blockIdx.x*128;

    // output demux
    float* Cout; const float* bias; int outN, colbase; float alpha;
    if (MODE == 0){
        int seg = n0 >> 10;
        Cout = (seg==0) ? g_Q : (seg==1) ? g_K : (seg==2) ? g_V : g_D;
        bias = (seg==0) ? bq : (seg==1) ? bk : (seg==2) ? bv : bd;
        outN = (seg<3) ? DIMN : HL;
        colbase = (seg<3) ? (n0 & 1023) : (n0 - 3072);
        alpha = (seg==0) ? 0.125f : 1.f;
    } else {
        Cout = OutM1; bias = bq; outN = DIMN; colbase = n0; alpha = 1.f;
    }

    // loaders: 2 ops each for A and B per chunk; op o: row=o>>2, ch=o&3
    const int lrow = tid >> 2, lch = tid & 3;
    const __half* ap[2]; const __half* bp[2];
    uint32_t aoff[2], boff[2];
    #pragma unroll
    for (int i=0;i<2;i++){
        int row = lrow + i*64;
        int gr = m0 + row;
        if (MODE == 0){
            int bb = gr >> 12, ss = gr & 4095;
            ap[i] = Ah + (size_t)(ss*BATCH + bb)*DIMN + lch*8;
        } else {
            ap[i] = Ah + (size_t)gr*DIMN + lch*8;
        }
        bp[i] = Bh + (size_t)(n0 + row)*DIMN + lch*8;
        aoff[i] = (uint32_t)(row*HROW + lch*8)*2u;
        boff[i] = aoff[i];
    }

    // per-lane ldmatrix offsets (bytes within a stage)
    uint32_t aL[4], bL[2];
    #pragma unroll
    for (int fm=0;fm<4;fm++){
        int row = wm*64 + fm*16 + (lane & 7) + ((lane >> 3) & 1)*8;
        int kof = (lane >> 4)*8;
        aL[fm] = (uint32_t)(row*HROW + kof)*2u;
    }
    #pragma unroll
    for (int p=0;p<2;p++){
        int row = wn*32 + p*16 + (lane & 7) + ((lane >> 3) >> 1)*8;
        int kof = ((lane >> 3) & 1)*8;
        bL[p] = (uint32_t)(row*HROW + kof)*2u;
    }

    float acc[4][4][4];
    #pragma unroll
    for (int i=0;i<4;i++)
        #pragma unroll
        for (int j=0;j<4;j++)
            #pragma unroll
            for (int k=0;k<4;k++) acc[i][j][k]=0.f;

    #pragma unroll
    for (int s=0;s<STAGES-1;s++){
        #pragma unroll
        for (int i=0;i<2;i++){
            cpa16(sbase + s*HSTB + aoff[i], ap[i] + s*32);
            cpa16(bbase + s*HSTB + boff[i], bp[i] + s*32);
        }
        asm volatile("cp.async.commit_group;" ::: "memory");
    }

    for (int c = 0; c < 32; c++){
        asm volatile("cp.async.wait_group 2;" ::: "memory");
        __syncthreads();
        if (c + STAGES-1 < 32){
            int cc = c + STAGES-1, st = cc & (STAGES-1);
            #pragma unroll
            for (int i=0;i<2;i++){
                cpa16(sbase + st*HSTB + aoff[i], ap[i] + cc*32);
                cpa16(bbase + st*HSTB + boff[i], bp[i] + cc*32);
            }
        }
        asm volatile("cp.async.commit_group;" ::: "memory");

        const uint32_t aStage = sbase + (c & (STAGES-1))*HSTB;
        const uint32_t bStage = bbase + (c & (STAGES-1))*HSTB;
        #pragma unroll
        for (int kk=0;kk<2;kk++){
            uint32_t af[4][4], bf[2][4];
            #pragma unroll
            for (int fm=0;fm<4;fm++)
                ldsm4(af[fm], aStage + aL[fm] + kk*32);
            #pragma unroll
            for (int p=0;p<2;p++)
                ldsm4(bf[p], bStage + bL[p] + kk*32);
            #pragma unroll
            for (int fm=0;fm<4;fm++)
                #pragma unroll
                for (int fn=0;fn<4;fn++)
                    mma_f16(acc[fm][fn], af[fm], &bf[fn>>1][(fn&1)*2]);
        }
    }

    // ---- epilogue ----
    #pragma unroll
    for (int fm=0;fm<4;fm++){
        int r0 = m0 + wm*64 + fm*16 + g;
        int r1 = r0 + 8;
        size_t ob0, ob1;
        if (MODE == 0){
            ob0 = (size_t)r0*outN; ob1 = (size_t)r1*outN;
        } else {
            int bb0 = r0>>12, ss0 = r0&4095;
            int bb1 = r1>>12, ss1 = r1&4095;
            ob0 = (size_t)(ss0*BATCH+bb0)*DIMN;
            ob1 = (size_t)(ss1*BATCH+bb1)*DIMN;
        }
        #pragma unroll
        for (int fn=0;fn<4;fn++){
            int col = colbase + wn*32 + fn*8 + tig*2;
            float b0 = bias[col], b1 = bias[col+1];
            float2 v0 = make_float2(alpha*(acc[fm][fn][0]+b0),
                                    alpha*(acc[fm][fn][1]+b1));
            float2 v1 = make_float2(alpha*(acc[fm][fn][2]+b0),
                                    alpha*(acc[fm][fn][3]+b1));
            *(float2*)&Cout[ob0 + col] = v0;
            *(float2*)&Cout[ob1 + col] = v1;
        }
    }
}

// ---------------- row layernorm over DIM=1024, K and V in one launch ----------------
__global__ __launch_bounds__(256) void ln_rows_kv(
    const float* __restrict__ gamma, const float* __restrict__ beta)
{
    float* X = blockIdx.y ? g_V : g_K;
    int row = blockIdx.x;
    float* p = X + (size_t)row*DIMN;
    int tid = threadIdx.x;
    float4 v = *(float4*)(p + tid*4);
    float s  = v.x+v.y+v.z+v.w;
    float s2 = v.x*v.x+v.y*v.y+v.z*v.z+v.w*v.w;
    #pragma unroll
    for (int o=16;o>0;o>>=1){
        s  += __shfl_down_sync(0xffffffffu, s,  o);
        s2 += __shfl_down_sync(0xffffffffu, s2, o);
    }
    __shared__ float rs[8], rs2[8];
    int warp = tid>>5, lane = tid&31;
    if (lane==0){ rs[warp]=s; rs2[warp]=s2; }
    __syncthreads();
    if (tid==0){
        float S=0.f,S2=0.f;
        for(int i=0;i<8;i++){S+=rs[i];S2+=rs2[i];}
        float mean = S*(1.f/DIMN);
        float var  = S2*(1.f/DIMN) - mean*mean;
        rs[0]=mean; rs2[0]=rsqrtf(var + 1e-5f);
    }
    __syncthreads();
    float mean = rs[0], rstd = rs2[0];
    float4 g4 = *(const float4*)(gamma + tid*4);
    float4 b4 = *(const float4*)(beta  + tid*4);
    v.x = (v.x-mean)*rstd*g4.x + b4.x;
    v.y = (v.y-mean)*rstd*g4.y + b4.y;
    v.z = (v.z-mean)*rstd*g4.z + b4.z;
    v.w = (v.w-mean)*rstd*g4.w + b4.w;
    *(float4*)(p + tid*4) = v;
}

// ------- column softmax stats, split over sequence (partials) -------
__global__ __launch_bounds__(256) void colstats_part()
{
    int b  = blockIdx.x >> 4;
    int c0 = (blockIdx.x & 15) << 5;
    int sp = blockIdx.y;
    int cl = threadIdx.x & 31;
    int si = threadIdx.x >> 5;
    int c = c0 + cl;
    int sbeg = sp*(SEQ/NCS), send = sbeg + SEQ/NCS;
    float m = -1e30f, sum = 0.f;
    for (int s = sbeg + si; s < send; s += 8){
        float v = g_D[((size_t)(b*SEQ + s))*HL + c];
        if (v > m){ sum *= __expf(m - v); m = v; }
        sum += __expf(v - m);
    }
    __shared__ float sm[8][32], ss[8][32];
    sm[si][cl]=m; ss[si][cl]=sum;
    __syncthreads();
    if (si == 0){
        float M = sm[0][cl];
        #pragma unroll
        for (int k=1;k<8;k++) M = fmaxf(M, sm[k][cl]);
        float S = 0.f;
        #pragma unroll
        for (int k=0;k<8;k++) S += ss[k][cl]*__expf(sm[k][cl]-M);
        g_pm[sp][b*HL + c] = M;
        g_ps[sp][b*HL + c] = S;
    }
}

__global__ __launch_bounds__(256) void colstats_reduce()
{
    int i = blockIdx.x*256 + threadIdx.x;
    float M = g_pm[0][i];
    #pragma unroll
    for (int k=1;k<NCS;k++) M = fmaxf(M, g_pm[k][i]);
    float S = 0.f;
    #pragma unroll
    for (int k=0;k<NCS;k++) S += g_ps[k][i]*__expf(g_pm[k][i]-M);
    g_cmax[i] = M;
    g_cinv[i] = 1.f/S;
}

// ----- compressed landmarks, split over sequence (partials), 16-row tiles -----
__global__ __launch_bounds__(256) void compress_part()
{
    int b = blockIdx.x >> 4;
    int h = blockIdx.x & 15;
    int ch = blockIdx.y;
    int tid = threadIdx.x;
    int d  = tid & 63;
    int lg = tid >> 6;
    __shared__ float wsh[16][32];
    __shared__ float ksh[16][64];
    __shared__ float vsh[16][64];
    __shared__ float msh[32], ish[32];
    if (tid < 32){
        msh[tid] = g_cmax[b*HL + h*32 + tid];
        ish[tid] = g_cinv[b*HL + h*32 + tid];
    }
    __syncthreads();
    float kacc[8], vacc[8];
    #pragma unroll
    for (int i=0;i<8;i++){ kacc[i]=0.f; vacc[i]=0.f; }

    int sbeg = ch*(SEQ/NCH), send = sbeg + SEQ/NCH;
    for (int s0=sbeg; s0<send; s0+=16){
        #pragma unroll
        for (int r=0;r<2;r++){
            int e = tid + r*256;
            int si = e >> 5, l = e & 31;
            float dv = g_D[((size_t)(b*SEQ + s0 + si))*HL + h*32 + l];
            wsh[si][l] = __expf(dv - msh[l]) * ish[l];
        }
        #pragma unroll
        for (int r=0;r<4;r++){
            int e = tid + r*256;
            int si = e >> 6, dd = e & 63;
            size_t off = ((size_t)(b*SEQ + s0 + si))*DIMN + h*64 + dd;
            ksh[si][dd] = g_K[off];
            vsh[si][dd] = g_V[off];
        }
        __syncthreads();
        #pragma unroll
        for (int si=0; si<16; si++){
            float kv = ksh[si][d], vv = vsh[si][d];
            #pragma unroll
            for (int i=0;i<8;i++){
                float w = wsh[si][lg*8+i];
                kacc[i] += w*kv; vacc[i] += w*vv;
            }
        }
        __syncthreads();
    }
    #pragma unroll
    for (int i=0;i<8;i++){
        int l = lg*8+i;
        size_t off = (((size_t)(b*NH+h))*LLC + l)*DHD + d;
        g_pKc[ch][off] = kacc[i];
        g_pVc[ch][off] = vacc[i];
    }
}

__global__ __launch_bounds__(256) void compress_reduce()
{
    int i = blockIdx.x*256 + threadIdx.x;
    float sk = 0.f, sv = 0.f;
    #pragma unroll
    for (int c=0;c<NCH;c++){ sk += g_pKc[c][i]; sv += g_pVc[c][i]; }
    g_Kc[i] = sk;
    g_Vc[i] = sv;
}

// ---- layernorm of Kc/Vc over (h,d) for each (b,l), both in one launch ----
__global__ __launch_bounds__(256) void ln_small2(
    const float* __restrict__ gamma, const float* __restrict__ beta)
{
    float* X = blockIdx.y ? g_Vc : g_Kc;
    int b = blockIdx.x >> 5;
    int l = blockIdx.x & 31;
    int tid = threadIdx.x;
    float vals[4];
    float s=0.f, s2=0.f;
    #pragma unroll
    for (int k=0;k<4;k++){
        int e = tid + k*256;
        int h = e >> 6, dd = e & 63;
        float v = X[(((size_t)(b*NH+h))*LLC + l)*DHD + dd];
        vals[k]=v; s+=v; s2+=v*v;
    }
    #pragma unroll
    for (int o=16;o>0;o>>=1){
        s  += __shfl_down_sync(0xffffffffu, s,  o);
        s2 += __shfl_down_sync(0xffffffffu, s2, o);
    }
    __shared__ float rs[8], rs2[8];
    int warp = tid>>5, lane = tid&31;
    if (lane==0){ rs[warp]=s; rs2[warp]=s2; }
    __syncthreads();
    if (tid==0){
        float S=0.f,S2=0.f;
        for(int i=0;i<8;i++){S+=rs[i];S2+=rs2[i];}
        float mean = S*(1.f/DIMN);
        float var  = S2*(1.f/DIMN) - mean*mean;
        rs[0]=mean; rs2[0]=rsqrtf(var + 1e-5f);
    }
    __syncthreads();
    float mean = rs[0], rstd = rs2[0];
    #pragma unroll
    for (int k=0;k<4;k++){
        int e = tid + k*256;
        int h = e >> 6, dd = e & 63;
        X[(((size_t)(b*NH+h))*LLC + l)*DHD + dd] =
            (vals[k]-mean)*rstd*gamma[e] + beta[e];
    }
}

// ---------------- fused attention: 32 query rows per block ----------------
#define ATP 68
#define AT_Q   0
#define AT_KC  (32*ATP)
#define AT_VC  (64*ATP)
#define AT_KW  (96*ATP)
#define AT_VW  (136*ATP)
#define AT_PR  (176*ATP)
#define AT_SMEM ((176*ATP + 32*48)*4)   // 54016 bytes

__global__ __launch_bounds__(256) void attn32()
{
    extern __shared__ float s[];
    const int t = threadIdx.x;
    const int h = blockIdx.y, b = blockIdx.z;
    const int s0 = blockIdx.x*32;

    #pragma unroll
    for (int r=0;r<2;r++){
        int e = t + r*256;
        int row = e >> 4, c4 = (e & 15)*4;
        *(float4*)&s[AT_Q + row*ATP + c4] =
            *(const float4*)&g_Q[((size_t)(b*SEQ + s0 + row))*DIMN + h*64 + c4];
        size_t off = (((size_t)(b*NH+h))*LLC + row)*DHD + c4;
        *(float4*)&s[AT_KC + row*ATP + c4] = *(const float4*)&g_Kc[off];
        *(float4*)&s[AT_VC + row*ATP + c4] = *(const float4*)&g_Vc[off];
    }
    #pragma unroll
    for (int r=0;r<3;r++){
        int e = t + r*256;
        if (e < 640){
            int row = e >> 4, c4 = (e & 15)*4;
            int pos = s0 - EEXT + row;
            float4 kz = make_float4(0,0,0,0), vz = make_float4(0,0,0,0);
            if (pos >= 0 && pos < SEQ){
                size_t off = ((size_t)(b*SEQ+pos))*DIMN + h*64 + c4;
                kz = *(const float4*)&g_K[off];
                vz = *(const float4*)&g_V[off];
            }
            *(float4*)&s[AT_KW + row*ATP + c4] = kz;
            *(float4*)&s[AT_VW + row*ATP + c4] = vz;
        }
    }
    __syncthreads();

    const int w = t >> 3, j8 = t & 7;
    const int gl = w >> 3;
    const float* qr = &s[AT_Q + w*ATP];
    const float* krs[6];
    #pragma unroll
    for (int m=0;m<6;m++){
        int j = j8 + 8*m;
        krs[m] = (j < 32) ? &s[AT_KC + j*ATP]
                          : &s[AT_KW + (gl*8 + (j-32))*ATP];
    }
    float lg[6] = {0,0,0,0,0,0};
    #pragma unroll
    for (int c4=0;c4<16;c4++){
        float4 qv = *(const float4*)(qr + c4*4);
        #pragma unroll
        for (int m=0;m<6;m++){
            float4 kv = *(const float4*)(krs[m] + c4*4);
            lg[m] += qv.x*kv.x + qv.y*kv.y + qv.z*kv.z + qv.w*kv.w;
        }
    }
    #pragma unroll
    for (int m=4;m<6;m++){
        int jj = j8 + 8*m - 32;
        int pos = s0 + gl*8 - EEXT + jj;
        if (pos < 0 || pos >= SEQ) lg[m] = -1e30f;
    }
    float mx = lg[0];
    #pragma unroll
    for (int m=1;m<6;m++) mx = fmaxf(mx, lg[m]);
    #pragma unroll
    for (int o=4;o>0;o>>=1) mx = fmaxf(mx, __shfl_xor_sync(0xffffffffu, mx, o, 8));
    float sum = 0.f;
    #pragma unroll
    for (int m=0;m<6;m++){ lg[m] = __expf(lg[m]-mx); sum += lg[m]; }
    #pragma unroll
    for (int o=4;o>0;o>>=1) sum += __shfl_xor_sync(0xffffffffu, sum, o, 8);
    float inv = 1.f/sum;
    #pragma unroll
    for (int m=0;m<6;m++) s[AT_PR + w*48 + j8 + 8*m] = lg[m]*inv;
    __syncthreads();

    const int d8 = (t & 7)*8;
    float4 oa = make_float4(0,0,0,0), ob = make_float4(0,0,0,0);
    const float* pr = &s[AT_PR + w*48];
    #pragma unroll
    for (int j=0;j<32;j++){
        float p = pr[j];
        const float* vr = &s[AT_VC + j*ATP + d8];
        float4 va = *(const float4*)vr, vb = *(const float4*)(vr+4);
        oa.x += p*va.x; oa.y += p*va.y; oa.z += p*va.z; oa.w += p*va.w;
        ob.x += p*vb.x; ob.y += p*vb.y; ob.z += p*vb.z; ob.w += p*vb.w;
    }
    #pragma unroll
    for (int j=0;j<16;j++){
        float p = pr[32+j];
        const float* vr = &s[AT_VW + (gl*8+j)*ATP + d8];
        float4 va = *(const float4*)vr, vb = *(const float4*)(vr+4);
        oa.x += p*va.x; oa.y += p*va.y; oa.z += p*va.z; oa.w += p*va.w;
        ob.x += p*vb.x; ob.y += p*vb.y; ob.z += p*vb.z; ob.w += p*vb.w;
    }
    // store fp16 directly: feeds the fp16 output GEMM
    __half2 h0 = __floats2half2_rn(oa.x, oa.y);
    __half2 h1 = __floats2half2_rn(oa.z, oa.w);
    __half2 h2 = __floats2half2_rn(ob.x, ob.y);
    __half2 h3 = __floats2half2_rn(ob.z, ob.w);
    uint4 pk = make_uint4(*(uint32_t*)&h0, *(uint32_t*)&h1,
                          *(uint32_t*)&h2, *(uint32_t*)&h3);
    size_t obase = ((size_t)(b*SEQ + s0 + w))*DIMN + h*64 + d8;
    *(uint4*)&g_Ch[obase] = pk;
}

// ---------------- launch ----------------
extern "C" void kernel_launch(void* const* d_in, const int* in_sizes, int n_in,
                              void* d_out, int out_size)
{
    const float* query = (const float*)d_in[0];
    const float* Wq = (const float*)d_in[1];
    const float* bq = (const float*)d_in[2];
    const float* Wk = (const float*)d_in[3];
    const float* bk = (const float*)d_in[4];
    const float* Wv = (const float*)d_in[5];
    const float* bv = (const float*)d_in[6];
    const float* Wo = (const float*)d_in[7];
    const float* bo = (const float*)d_in[8];
    const float* gl = (const float*)d_in[9];
    const float* bl = (const float*)d_in[10];
    const float* gs = (const float*)d_in[11];
    const float* bs = (const float*)d_in[12];
    const float* Wd = (const float*)d_in[13];
    const float* bd = (const float*)d_in[14];
    float* out = (float*)d_out;

    __half *Xh, *WcatH, *WoTh, *Ch;
    cudaGetSymbolAddress((void**)&Xh,    g_Xh);
    cudaGetSymbolAddress((void**)&WcatH, g_WcatH);
    cudaGetSymbolAddress((void**)&WoTh,  g_WoTh);
    cudaGetSymbolAddress((void**)&Ch,    g_Ch);

    static int cfg = 0;
    if (!cfg){
        cudaFuncSetAttribute(gemm_h<0>, cudaFuncAttributeMaxDynamicSharedMemorySize, GH_SMEM);
        cudaFuncSetAttribute(gemm_h<1>, cudaFuncAttributeMaxDynamicSharedMemorySize, GH_SMEM);
        cudaFuncSetAttribute(attn32,    cudaFuncAttributeMaxDynamicSharedMemorySize, AT_SMEM);
        cfg = 1;
    }

    const int X4 = MROWS*DIMN/4;       // 4194304 -> 16384 blocks

    // operand conversion: X -> half, W -> transposed half
    round_half<<<X4/256, 256>>>(query, Xh, X4);
    pack_wT<<<dim3(NCAT/32, DIMN/32), dim3(32,8)>>>(Wq, Wk, Wv, Wd);
    pack_woT<<<dim3(DIMN/32, DIMN/32), dim3(32,8)>>>(Wo);

    // fused Q/K/V/D projection (fp16 HMMA, one launch)
    gemm_h<0><<<dim3(28,128), 256, GH_SMEM>>>(Xh, WcatH, bq, bk, bv, bd, nullptr);

    // K/V layernorm (g_l, b_l)
    ln_rows_kv<<<dim3(MROWS,2), 256>>>(gl, bl);

    // head-score column softmax (split + reduce)
    colstats_part<<<dim3(64, NCS), 256>>>();
    colstats_reduce<<<8, 256>>>();

    // landmark compression (split + reduce)
    compress_part<<<dim3(64, NCH), 256>>>();
    compress_reduce<<<KCN/256, 256>>>();

    // landmark layernorm (g_s, b_s)
    ln_small2<<<dim3(BATCH*LLC, 2), 256>>>(gs, bs);

    // fused compressed + windowed attention (writes fp16 g_Ch)
    attn32<<<dim3(NGRP/4, NH, BATCH), 256, AT_SMEM>>>();

    // output projection (fp16 HMMA), scattered back to (S,B,DIM)
    gemm_h<1><<<dim3(8,128), 256, GH_SMEM>>>(Ch, WoTh, bo, nullptr, nullptr, nullptr, out);
}